// round 14
// baseline (speedup 1.0000x reference)
#include <cuda_runtime.h>
#include <cuda_bf16.h>
#include <cstddef>
#include <cstdint>

// ---------------- fixed problem constants ----------------
#define NTOK 2048
#define DMODEL 1280
#define NHEAD 16
#define KDIM 80
#define HALFK 40
#define NLAYER 4
#define FDIM 5120
#define GPOS 48
#define OUTD 2048
#define TPI 512
#define NIMG 4

// ---------------- scratch ----------------
__device__ float g_x[NTOK * DMODEL];
__device__ float g_hdn[NTOK * DMODEL];
__device__ float g_qkv[NTOK * 3 * DMODEL];
__device__ float g_obuf[NTOK * DMODEL];
__device__ float g_ff[NTOK * FDIM];
__device__ float g_cos[NTOK * HALFK];
__device__ float g_sin[NTOK * HALFK];
__device__ int g_row[NTOK], g_col[NTOK], g_h[NTOK], g_w4[NTOK];

// ---------------- helpers ----------------
__device__ __forceinline__ float gelu_tanh(float v) {
    const float c = 0.7978845608028654f;
    float t = tanhf(c * (v + 0.044715f * v * v * v));
    return 0.5f * v * (1.0f + t);
}
__device__ __forceinline__ float warp_sum(float v) {
    #pragma unroll
    for (int o = 16; o > 0; o >>= 1) v += __shfl_xor_sync(0xffffffffu, v, o);
    return v;
}
__device__ __forceinline__ uint32_t f2tf32(float f) {
    uint32_t r;
    asm("cvt.rna.tf32.f32 %0, %1;" : "=r"(r) : "f"(f));
    return r;
}
__device__ __forceinline__ float f2tf32f(float f) {
    return __uint_as_float(f2tf32(f));
}
__device__ __forceinline__ void mma_tf32(float& c0, float& c1, float& c2, float& c3,
                                         uint32_t a0, uint32_t a1, uint32_t a2, uint32_t a3,
                                         uint32_t b0, uint32_t b1) {
    asm volatile(
        "mma.sync.aligned.m16n8k8.row.col.f32.tf32.tf32.f32 "
        "{%0,%1,%2,%3}, {%4,%5,%6,%7}, {%8,%9}, {%0,%1,%2,%3};"
        : "+f"(c0), "+f"(c1), "+f"(c2), "+f"(c3)
        : "r"(a0), "r"(a1), "r"(a2), "r"(a3), "r"(b0), "r"(b1));
}
__device__ __forceinline__ void cp16(float* smem_ptr, const float* gptr) {
    uint32_t s = (uint32_t)__cvta_generic_to_shared(smem_ptr);
    asm volatile("cp.async.cg.shared.global [%0], [%1], 16;" :: "r"(s), "l"(gptr));
}

// ---------------- token coords ----------------
__global__ void coords_kernel(const int* __restrict__ grid, int n_imgs) {
    int t = blockIdx.x * blockDim.x + threadIdx.x;
    if (t >= NTOK) return;
    int acc = 0, local = 0, h = 1, w = 1;
    for (int i = 0; i < n_imgs; i++) {
        int tpi = grid[i * 3] * grid[i * 3 + 1] * grid[i * 3 + 2];
        if (t >= acc && t < acc + tpi) {
            local = t - acc; h = grid[i * 3 + 1]; w = grid[i * 3 + 2];
        }
        acc += tpi;
    }
    int spatial = local % (h * w);
    int group = spatial / 4, intra = spatial % 4;
    int mw = w / 2;
    g_row[t] = (group / mw) * 2 + intra / 2;
    g_col[t] = (group % mw) * 2 + intra % 2;
    g_h[t] = h; g_w4[t] = w;
}

// ---------------- rope cos/sin table ----------------
__global__ void ropetab_kernel() {
    int id = blockIdx.x * blockDim.x + threadIdx.x;
    if (id >= NTOK * HALFK) return;
    int n = id / HALFK, j = id % HALFK;
    int jj = j % 20;
    float pos = (float)((j < 20) ? g_row[n] : g_col[n]);
    float inv_freq = powf(10000.0f, -(float)jj / 20.0f);
    float f = pos * inv_freq;
    g_cos[id] = cosf(f);
    g_sin[id] = sinf(f);
}

// ---------------- round fp32 -> tf32 elementwise ----------------
__global__ void round_kernel(const float* __restrict__ in, float* __restrict__ out, int n4) {
    int i = blockIdx.x * blockDim.x + threadIdx.x;
    if (i >= n4) return;
    float4 v = ((const float4*)in)[i];
    ((float4*)out)[i] = make_float4(f2tf32f(v.x), f2tf32f(v.y), f2tf32f(v.z), f2tf32f(v.w));
}

// ---------------- bilinear pos-embed add ----------------
__global__ void posembed_kernel(const float* __restrict__ pos_embed, float* __restrict__ x) {
    int n = blockIdx.x;
    int row = g_row[n], col = g_col[n], h = g_h[n], w = g_w4[n];
    float rf = (h > 1) ? (float)row * (float)(GPOS - 1) / (float)(h - 1 > 1 ? h - 1 : 1) : 0.0f;
    float cf = (w > 1) ? (float)col * (float)(GPOS - 1) / (float)(w - 1 > 1 ? w - 1 : 1) : 0.0f;
    int r0 = (int)floorf(rf), c0 = (int)floorf(cf);
    int r1 = min(r0 + 1, GPOS - 1), c1 = min(c0 + 1, GPOS - 1);
    float wr = rf - (float)r0, wc = cf - (float)c0;
    float w00 = (1 - wr) * (1 - wc), w01 = (1 - wr) * wc, w10 = wr * (1 - wc), w11 = wr * wc;
    const float* p00 = pos_embed + (size_t)(r0 * GPOS + c0) * DMODEL;
    const float* p01 = pos_embed + (size_t)(r0 * GPOS + c1) * DMODEL;
    const float* p10 = pos_embed + (size_t)(r1 * GPOS + c0) * DMODEL;
    const float* p11 = pos_embed + (size_t)(r1 * GPOS + c1) * DMODEL;
    float* xr = x + (size_t)n * DMODEL;
    for (int d = threadIdx.x; d < DMODEL; d += blockDim.x)
        xr[d] += p00[d] * w00 + p01[d] * w01 + p10[d] * w10 + p11[d] * w11;
}

// ---------------- single-pass layernorm (output tf32-rounded) ----------------
__global__ void layernorm_kernel(const float* __restrict__ x, const float* __restrict__ s,
                                 const float* __restrict__ b, float* __restrict__ out, int cols) {
    int r = blockIdx.x, tid = threadIdx.x;
    const float* xr = x + (size_t)r * cols;
    __shared__ float red[8], red2[8];
    float sum = 0.0f, ss = 0.0f;
    for (int c = tid; c < cols; c += 256) { float v = xr[c]; sum += v; ss += v * v; }
    sum = warp_sum(sum);
    ss = warp_sum(ss);
    if ((tid & 31) == 0) { red[tid >> 5] = sum; red2[tid >> 5] = ss; }
    __syncthreads();
    float tot = 0.0f, tot2 = 0.0f;
    #pragma unroll
    for (int i = 0; i < 8; i++) { tot += red[i]; tot2 += red2[i]; }
    float mu = tot / (float)cols;
    float var = fmaxf(tot2 / (float)cols - mu * mu, 0.0f);
    float inv = rsqrtf(var + 1e-6f);
    float* orow = out + (size_t)r * cols;
    for (int c = tid; c < cols; c += 256)
        orow[c] = f2tf32f((xr[c] - mu) * inv * s[c] + b[c]);
}

// ---------------- tf32 GEMM, 3-stage cp.async, 128x128 tile (1 CTA/SM) ----------------
#define AP 36
#define BP 132
#define ASZ (128 * AP)
#define ASZ2 (64 * AP)
#define BSZ (32 * BP)
#define ST128 3
#define ST64 2
__global__ void __launch_bounds__(256, 1)
tf32_gemm(const float* __restrict__ A, const float* __restrict__ W,
          const float* __restrict__ bias, const float* __restrict__ res,
          float* __restrict__ C, int MM, int NN, int KK, int epi, int rnd) {
    extern __shared__ float smem[];
    float* As = smem;
    float* Bs = smem + ST128 * ASZ;
    const int tid = threadIdx.x;
    const int warp = tid >> 5, lane = tid & 31;
    const int wm = warp & 1, wn = warp >> 1;
    const int g = lane >> 2, c = lane & 3;
    const int m0 = blockIdx.y * 128, n0 = blockIdx.x * 128;

    const int arow = tid >> 3, acol = (tid & 7) << 2;
    const int brow = tid >> 5, bcol = (tid & 31) << 2;

    float acc[4][4][4];
    #pragma unroll
    for (int i = 0; i < 4; i++)
        #pragma unroll
        for (int j = 0; j < 4; j++)
            #pragma unroll
            for (int r = 0; r < 4; r++) acc[i][j][r] = 0.0f;

    const int T = KK >> 5;

    // prologue: issue stages 0..ST128-2
    #pragma unroll
    for (int t = 0; t < ST128 - 1; t++) {
        const int ko = t << 5;
        float* as = As + t * ASZ;
        float* bs = Bs + t * BSZ;
        #pragma unroll
        for (int i = 0; i < 4; i++) {
            cp16(as + (arow + i * 32) * AP + acol,
                 A + (size_t)(m0 + arow + i * 32) * KK + ko + acol);
            cp16(bs + (brow + i * 8) * BP + bcol,
                 W + (size_t)(ko + brow + i * 8) * NN + n0 + bcol);
        }
        asm volatile("cp.async.commit_group;");
    }

    for (int t = 0; t < T; ++t) {
        if (t + ST128 - 1 < T) {
            const int st = (t + ST128 - 1) % ST128;
            const int ko = (t + ST128 - 1) << 5;
            float* as = As + st * ASZ;
            float* bs = Bs + st * BSZ;
            #pragma unroll
            for (int i = 0; i < 4; i++) {
                cp16(as + (arow + i * 32) * AP + acol,
                     A + (size_t)(m0 + arow + i * 32) * KK + ko + acol);
                cp16(bs + (brow + i * 8) * BP + bcol,
                     W + (size_t)(ko + brow + i * 8) * NN + n0 + bcol);
            }
        }
        asm volatile("cp.async.commit_group;");
        asm volatile("cp.async.wait_group %0;" :: "n"(ST128 - 1));
        __syncthreads();

        const uint32_t* AsB = reinterpret_cast<const uint32_t*>(As + (t % ST128) * ASZ);
        const float* BsF = Bs + (t % ST128) * BSZ;
        #pragma unroll
        for (int kk = 0; kk < 4; kk++) {
            const int kb = kk * 8;
            uint32_t af[4][4];
            #pragma unroll
            for (int mi = 0; mi < 4; mi++) {
                int r = wm * 64 + mi * 16;
                af[mi][0] = AsB[(r + g) * AP + kb + c];
                af[mi][1] = AsB[(r + g + 8) * AP + kb + c];
                af[mi][2] = AsB[(r + g) * AP + kb + c + 4];
                af[mi][3] = AsB[(r + g + 8) * AP + kb + c + 4];
            }
            uint32_t bf[4][2];
            #pragma unroll
            for (int ni = 0; ni < 4; ni++) {
                int col = wn * 32 + ni * 8;
                bf[ni][0] = f2tf32(BsF[(kb + c) * BP + col + g]);
                bf[ni][1] = f2tf32(BsF[(kb + c + 4) * BP + col + g]);
            }
            #pragma unroll
            for (int mi = 0; mi < 4; mi++)
                #pragma unroll
                for (int ni = 0; ni < 4; ni++)
                    mma_tf32(acc[mi][ni][0], acc[mi][ni][1], acc[mi][ni][2], acc[mi][ni][3],
                             af[mi][0], af[mi][1], af[mi][2], af[mi][3],
                             bf[ni][0], bf[ni][1]);
        }
        __syncthreads();
    }

    #pragma unroll
    for (int mi = 0; mi < 4; mi++) {
        #pragma unroll
        for (int ni = 0; ni < 4; ni++) {
            int r0r = m0 + wm * 64 + mi * 16 + g;
            int cn = n0 + wn * 32 + ni * 8 + 2 * c;
            #pragma unroll
            for (int half = 0; half < 2; half++) {
                int r = r0r + half * 8;
                float v0 = acc[mi][ni][half * 2 + 0] + bias[cn];
                float v1 = acc[mi][ni][half * 2 + 1] + bias[cn + 1];
                if (res) {
                    v0 += res[(size_t)r * NN + cn];
                    v1 += res[(size_t)r * NN + cn + 1];
                }
                if (epi) { v0 = gelu_tanh(v0); v1 = gelu_tanh(v1); }
                if (rnd) { v0 = f2tf32f(v0); v1 = f2tf32f(v1); }
                *(float2*)(C + (size_t)r * NN + cn) = make_float2(v0, v1);
            }
        }
    }
}

// ---------------- tf32 GEMM, 64x128 tile, 2-stage, 3 CTAs/SM ----------------
__global__ void __launch_bounds__(256, 3)
tf32_gemm64(const float* __restrict__ A, const float* __restrict__ W,
            const float* __restrict__ bias, const float* __restrict__ res,
            float* __restrict__ C, int MM, int NN, int KK, int epi, int rnd) {
    extern __shared__ float smem[];
    float* As = smem;
    float* Bs = smem + ST64 * ASZ2;
    const int tid = threadIdx.x;
    const int warp = tid >> 5, lane = tid & 31;
    const int wm = warp & 1, wn = warp >> 1;
    const int g = lane >> 2, c = lane & 3;
    const int m0 = blockIdx.y * 64, n0 = blockIdx.x * 128;

    const int arow = tid >> 3, acol = (tid & 7) << 2;
    const int brow = tid >> 5, bcol = (tid & 31) << 2;

    float acc[2][4][4];
    #pragma unroll
    for (int i = 0; i < 2; i++)
        #pragma unroll
        for (int j = 0; j < 4; j++)
            #pragma unroll
            for (int r = 0; r < 4; r++) acc[i][j][r] = 0.0f;

    const int T = KK >> 5;

    #pragma unroll
    for (int i = 0; i < 2; i++)
        cp16(As + (arow + i * 32) * AP + acol, A + (size_t)(m0 + arow + i * 32) * KK + acol);
    #pragma unroll
    for (int i = 0; i < 4; i++)
        cp16(Bs + (brow + i * 8) * BP + bcol, W + (size_t)(brow + i * 8) * NN + n0 + bcol);
    asm volatile("cp.async.commit_group;");

    for (int t = 0; t < T; ++t) {
        if (t + 1 < T) {
            const int st = (t + 1) & 1;
            const int ko = (t + 1) << 5;
            float* as = As + st * ASZ2;
            float* bs = Bs + st * BSZ;
            #pragma unroll
            for (int i = 0; i < 2; i++)
                cp16(as + (arow + i * 32) * AP + acol,
                     A + (size_t)(m0 + arow + i * 32) * KK + ko + acol);
            #pragma unroll
            for (int i = 0; i < 4; i++)
                cp16(bs + (brow + i * 8) * BP + bcol,
                     W + (size_t)(ko + brow + i * 8) * NN + n0 + bcol);
        }
        asm volatile("cp.async.commit_group;");
        asm volatile("cp.async.wait_group 1;");
        __syncthreads();

        const uint32_t* AsB = reinterpret_cast<const uint32_t*>(As + (t & 1) * ASZ2);
        const float* BsF = Bs + (t & 1) * BSZ;
        #pragma unroll
        for (int kk = 0; kk < 4; kk++) {
            const int kb = kk * 8;
            uint32_t af[2][4];
            #pragma unroll
            for (int mi = 0; mi < 2; mi++) {
                int r = wm * 32 + mi * 16;
                af[mi][0] = AsB[(r + g) * AP + kb + c];
                af[mi][1] = AsB[(r + g + 8) * AP + kb + c];
                af[mi][2] = AsB[(r + g) * AP + kb + c + 4];
                af[mi][3] = AsB[(r + g + 8) * AP + kb + c + 4];
            }
            uint32_t bf[4][2];
            #pragma unroll
            for (int ni = 0; ni < 4; ni++) {
                int col = wn * 32 + ni * 8;
                bf[ni][0] = f2tf32(BsF[(kb + c) * BP + col + g]);
                bf[ni][1] = f2tf32(BsF[(kb + c + 4) * BP + col + g]);
            }
            #pragma unroll
            for (int mi = 0; mi < 2; mi++)
                #pragma unroll
                for (int ni = 0; ni < 4; ni++)
                    mma_tf32(acc[mi][ni][0], acc[mi][ni][1], acc[mi][ni][2], acc[mi][ni][3],
                             af[mi][0], af[mi][1], af[mi][2], af[mi][3],
                             bf[ni][0], bf[ni][1]);
        }
        __syncthreads();
    }

    #pragma unroll
    for (int mi = 0; mi < 2; mi++) {
        #pragma unroll
        for (int ni = 0; ni < 4; ni++) {
            int r0r = m0 + wm * 32 + mi * 16 + g;
            int cn = n0 + wn * 32 + ni * 8 + 2 * c;
            #pragma unroll
            for (int half = 0; half < 2; half++) {
                int r = r0r + half * 8;
                float v0 = acc[mi][ni][half * 2 + 0] + bias[cn];
                float v1 = acc[mi][ni][half * 2 + 1] + bias[cn + 1];
                if (res) {
                    v0 += res[(size_t)r * NN + cn];
                    v1 += res[(size_t)r * NN + cn + 1];
                }
                if (epi) { v0 = gelu_tanh(v0); v1 = gelu_tanh(v1); }
                if (rnd) { v0 = f2tf32f(v0); v1 = f2tf32f(v1); }
                *(float2*)(C + (size_t)r * NN + cn) = make_float2(v0, v1);
            }
        }
    }
}

// ---------------- rope in-place on qkv buffer ----------------
__global__ void rope_kernel(float* __restrict__ qkv) {
    int id = blockIdx.x * blockDim.x + threadIdx.x;
    if (id >= NTOK * NHEAD * HALFK) return;
    int n = id / (NHEAD * HALFK);
    int rest = id % (NHEAD * HALFK);
    int h = rest / HALFK, i = rest % HALFK;
    float c = g_cos[n * HALFK + i], s = g_sin[n * HALFK + i];
    size_t base = (size_t)n * (3 * DMODEL) + h * KDIM;
    float* q = qkv + base;
    float* k = qkv + base + DMODEL;
    float q1 = q[i], q2 = q[i + HALFK];
    q[i] = q1 * c - q2 * s;
    q[i + HALFK] = q2 * c + q1 * s;
    float k1 = k[i], k2 = k[i + HALFK];
    k[i] = k1 * c - k2 * s;
    k[i + HALFK] = k2 * c + k1 * s;
}

// ---------------- fused flash attention (R7-exact) ----------------
#define QP 84
#define VP 88
#define PPP 68
#define FA_FLOATS (64 * QP + 64 * QP + 64 * VP + 64 * PPP + 256)
#define FA_SMEM (FA_FLOATS * 4)
#define SCALE 0.11180339887498949f
__global__ void __launch_bounds__(128)
flash_attn(const float* __restrict__ qkv, float* __restrict__ o) {
    extern __shared__ float fsm[];
    float* Qs = fsm;
    float* Ks = Qs + 64 * QP;
    float* Vs = Ks + 64 * QP;
    float* Ps = Vs + 64 * VP;
    float* rm = Ps + 64 * PPP;
    float* rs = rm + 128;

    const int h = blockIdx.y & 15, img = blockIdx.y >> 4;
    const int m0 = blockIdx.x * 64;
    const float* Qp = qkv + (size_t)img * TPI * (3 * DMODEL) + h * KDIM;
    const float* Kp = Qp + DMODEL;
    const float* Vp = Qp + 2 * DMODEL;

    const int tid = threadIdx.x;
    const int warp = tid >> 5, lane = tid & 31;
    const int wm = warp & 1, wn = warp >> 1;
    const int g = lane >> 2, c = lane & 3;

    #pragma unroll
    for (int i = 0; i < 10; i++) {
        int idx = tid + i * 128;
        int row = idx / 20, c4 = (idx % 20) * 4;
        float4 q4 = *(const float4*)(Qp + (size_t)(m0 + row) * (3 * DMODEL) + c4);
        *(float4*)(Qs + row * QP + c4) =
            make_float4(f2tf32f(q4.x), f2tf32f(q4.y), f2tf32f(q4.z), f2tf32f(q4.w));
    }

    float mrow[4], lrow[4], Oa[2][5][4];
    #pragma unroll
    for (int k = 0; k < 4; k++) { mrow[k] = -1e30f; lrow[k] = 0.0f; }
    #pragma unroll
    for (int mi = 0; mi < 2; mi++)
        #pragma unroll
        for (int ni = 0; ni < 5; ni++)
            #pragma unroll
            for (int r = 0; r < 4; r++) Oa[mi][ni][r] = 0.0f;

    const uint32_t* Qb = reinterpret_cast<const uint32_t*>(Qs);
    const uint32_t* Kb = reinterpret_cast<const uint32_t*>(Ks);
    const uint32_t* Vb = reinterpret_cast<const uint32_t*>(Vs);
    const uint32_t* Pb = reinterpret_cast<const uint32_t*>(Ps);

    for (int kc = 0; kc < 8; kc++) {
        const int k0 = kc * 64;
        #pragma unroll
        for (int i = 0; i < 10; i++) {
            int idx = tid + i * 128;
            int row = idx / 20, c4 = (idx % 20) * 4;
            float4 k4 = *(const float4*)(Kp + (size_t)(k0 + row) * (3 * DMODEL) + c4);
            *(float4*)(Ks + row * QP + c4) =
                make_float4(f2tf32f(k4.x), f2tf32f(k4.y), f2tf32f(k4.z), f2tf32f(k4.w));
            *(float4*)(Vs + row * VP + c4) =
                *(const float4*)(Vp + (size_t)(k0 + row) * (3 * DMODEL) + c4);
        }
        __syncthreads();

        float s[2][4][4];
        #pragma unroll
        for (int mi = 0; mi < 2; mi++)
            #pragma unroll
            for (int ni = 0; ni < 4; ni++)
                #pragma unroll
                for (int r = 0; r < 4; r++) s[mi][ni][r] = 0.0f;
        #pragma unroll
        for (int kb = 0; kb < 80; kb += 8) {
            uint32_t af[2][4];
            #pragma unroll
            for (int mi = 0; mi < 2; mi++) {
                int r = wm * 32 + mi * 16;
                af[mi][0] = Qb[(r + g) * QP + kb + c];
                af[mi][1] = Qb[(r + g + 8) * QP + kb + c];
                af[mi][2] = Qb[(r + g) * QP + kb + c + 4];
                af[mi][3] = Qb[(r + g + 8) * QP + kb + c + 4];
            }
            #pragma unroll
            for (int ni = 0; ni < 4; ni++) {
                int col = wn * 32 + ni * 8;
                uint32_t b0 = Kb[(col + g) * QP + kb + c];
                uint32_t b1 = Kb[(col + g) * QP + kb + c + 4];
                #pragma unroll
                for (int mi = 0; mi < 2; mi++)
                    mma_tf32(s[mi][ni][0], s[mi][ni][1], s[mi][ni][2], s[mi][ni][3],
                             af[mi][0], af[mi][1], af[mi][2], af[mi][3], b0, b1);
            }
        }
        float pmax[4] = {-1e30f, -1e30f, -1e30f, -1e30f};
        #pragma unroll
        for (int mi = 0; mi < 2; mi++)
            #pragma unroll
            for (int ni = 0; ni < 4; ni++)
                #pragma unroll
                for (int r = 0; r < 4; r++) {
                    s[mi][ni][r] *= SCALE;
                    int k = mi * 2 + (r >> 1);
                    pmax[k] = fmaxf(pmax[k], s[mi][ni][r]);
                }
        #pragma unroll
        for (int k = 0; k < 4; k++) {
            pmax[k] = fmaxf(pmax[k], __shfl_xor_sync(0xffffffffu, pmax[k], 1));
            pmax[k] = fmaxf(pmax[k], __shfl_xor_sync(0xffffffffu, pmax[k], 2));
        }
        if (c == 0) {
            #pragma unroll
            for (int k = 0; k < 4; k++) {
                int row = wm * 32 + (k >> 1) * 16 + (k & 1) * 8 + g;
                rm[row * 2 + wn] = pmax[k];
            }
        }
        __syncthreads();

        float alpha[4], psum[4] = {0.0f, 0.0f, 0.0f, 0.0f};
        #pragma unroll
        for (int k = 0; k < 4; k++) {
            int row = wm * 32 + (k >> 1) * 16 + (k & 1) * 8 + g;
            float mc = fmaxf(rm[row * 2], rm[row * 2 + 1]);
            float mn = fmaxf(mrow[k], mc);
            alpha[k] = __expf(mrow[k] - mn);
            mrow[k] = mn;
        }
        #pragma unroll
        for (int mi = 0; mi < 2; mi++)
            #pragma unroll
            for (int ni = 0; ni < 4; ni++)
                #pragma unroll
                for (int r = 0; r < 4; r++) {
                    int k = mi * 2 + (r >> 1);
                    float p = __expf(s[mi][ni][r] - mrow[k]);
                    s[mi][ni][r] = p;
                    psum[k] += p;
                }
        #pragma unroll
        for (int k = 0; k < 4; k++) {
            psum[k] += __shfl_xor_sync(0xffffffffu, psum[k], 1);
            psum[k] += __shfl_xor_sync(0xffffffffu, psum[k], 2);
        }
        if (c == 0) {
            #pragma unroll
            for (int k = 0; k < 4; k++) {
                int row = wm * 32 + (k >> 1) * 16 + (k & 1) * 8 + g;
                rs[row * 2 + wn] = psum[k];
            }
        }
        #pragma unroll
        for (int mi = 0; mi < 2; mi++)
            #pragma unroll
            for (int ni = 0; ni < 5; ni++)
                #pragma unroll
                for (int r = 0; r < 4; r++)
                    Oa[mi][ni][r] *= alpha[mi * 2 + (r >> 1)];
        #pragma unroll
        for (int mi = 0; mi < 2; mi++)
            #pragma unroll
            for (int ni = 0; ni < 4; ni++) {
                int row = wm * 32 + mi * 16 + g;
                int col = wn * 32 + ni * 8 + 2 * c;
                *(float2*)(Ps + row * PPP + col) =
                    make_float2(f2tf32f(s[mi][ni][0]), f2tf32f(s[mi][ni][1]));
                *(float2*)(Ps + (row + 8) * PPP + col) =
                    make_float2(f2tf32f(s[mi][ni][2]), f2tf32f(s[mi][ni][3]));
            }
        __syncthreads();

        #pragma unroll
        for (int k = 0; k < 4; k++) {
            int row = wm * 32 + (k >> 1) * 16 + (k & 1) * 8 + g;
            lrow[k] = lrow[k] * alpha[k] + rs[row * 2] + rs[row * 2 + 1];
        }

        #pragma unroll
        for (int kb = 0; kb < 64; kb += 8) {
            uint32_t af[2][4];
            #pragma unroll
            for (int mi = 0; mi < 2; mi++) {
                int r = wm * 32 + mi * 16;
                af[mi][0] = Pb[(r + g) * PPP + kb + c];
                af[mi][1] = Pb[(r + g + 8) * PPP + kb + c];
                af[mi][2] = Pb[(r + g) * PPP + kb + c + 4];
                af[mi][3] = Pb[(r + g + 8) * PPP + kb + c + 4];
            }
            #pragma unroll
            for (int ni = 0; ni < 5; ni++) {
                int col = wn * 40 + ni * 8;
                uint32_t b0 = Vb[(kb + c) * VP + col + g];
                uint32_t b1 = Vb[(kb + c + 4) * VP + col + g];
                #pragma unroll
                for (int mi = 0; mi < 2; mi++)
                    mma_tf32(Oa[mi][ni][0], Oa[mi][ni][1], Oa[mi][ni][2], Oa[mi][ni][3],
                             af[mi][0], af[mi][1], af[mi][2], af[mi][3], b0, b1);
            }
        }
        __syncthreads();
    }

    #pragma unroll
    for (int mi = 0; mi < 2; mi++)
        #pragma unroll
        for (int ni = 0; ni < 5; ni++)
            #pragma unroll
            for (int half = 0; half < 2; half++) {
                int k = mi * 2 + half;
                float inv = 1.0f / lrow[k];
                int row = img * TPI + m0 + wm * 32 + mi * 16 + g + half * 8;
                int col = h * KDIM + wn * 40 + ni * 8 + 2 * c;
                *(float2*)(o + (size_t)row * DMODEL + col) =
                    make_float2(f2tf32f(Oa[mi][ni][half * 2] * inv),
                                f2tf32f(Oa[mi][ni][half * 2 + 1] * inv));
            }
}

// ---------------- launch ----------------
extern "C" void kernel_launch(void* const* d_in, const int* in_sizes, int n_in,
                              void* d_out, int out_size) {
    const float* pixels   = (const float*)d_in[0];
    const int*   grid_thw = (const int*)d_in[1];
    const float* pos_embed= (const float*)d_in[2];
    const float* patch_w  = (const float*)d_in[3];
    const float* patch_b  = (const float*)d_in[4];
    const float* ln1_s    = (const float*)d_in[5];
    const float* ln1_b    = (const float*)d_in[6];
    const float* qkv_w    = (const float*)d_in[7];
    const float* qkv_b    = (const float*)d_in[8];
    const float* proj_w   = (const float*)d_in[9];
    const float* proj_b   = (const float*)d_in[10];
    const float* ln2_s    = (const float*)d_in[11];
    const float* ln2_b    = (const float*)d_in[12];
    const float* fc1_w    = (const float*)d_in[13];
    const float* fc1_b    = (const float*)d_in[14];
    const float* fc2_w    = (const float*)d_in[15];
    const float* fc2_b    = (const float*)d_in[16];
    const float* mn_s     = (const float*)d_in[17];
    const float* mn_b     = (const float*)d_in[18];
    const float* mfc1_w   = (const float*)d_in[19];
    const float* mfc1_b   = (const float*)d_in[20];
    const float* mfc2_w   = (const float*)d_in[21];
    const float* mfc2_b   = (const float*)d_in[22];
    float* out = (float*)d_out;

    float *px, *phdn, *pqkv, *pobuf, *pff;
    cudaGetSymbolAddress((void**)&px, g_x);
    cudaGetSymbolAddress((void**)&phdn, g_hdn);
    cudaGetSymbolAddress((void**)&pqkv, g_qkv);
    cudaGetSymbolAddress((void**)&pobuf, g_obuf);
    cudaGetSymbolAddress((void**)&pff, g_ff);

    const int SM128 = ST128 * (ASZ + BSZ) * 4;
    const int SM64  = ST64 * (ASZ2 + BSZ) * 4;
    cudaFuncSetAttribute(tf32_gemm, cudaFuncAttributeMaxDynamicSharedMemorySize, SM128);
    cudaFuncSetAttribute(tf32_gemm64, cudaFuncAttributeMaxDynamicSharedMemorySize, SM64);
    cudaFuncSetAttribute(flash_attn, cudaFuncAttributeMaxDynamicSharedMemorySize, FA_SMEM);

    int n_imgs = in_sizes[1] / 3;

    coords_kernel<<<(NTOK + 255) / 256, 256>>>(grid_thw, n_imgs);
    ropetab_kernel<<<(NTOK * HALFK + 255) / 256, 256>>>();

    round_kernel<<<(NTOK * 1536 / 4 + 255) / 256, 256>>>(pixels, pff, NTOK * 1536 / 4);
    tf32_gemm64<<<dim3(DMODEL / 128, NTOK / 64), 256, SM64>>>(
        pff, patch_w, patch_b, nullptr, px, NTOK, DMODEL, 1536, 0, 0);
    posembed_kernel<<<NTOK, 256>>>(pos_embed, px);

    for (int l = 0; l < NLAYER; ++l) {
        layernorm_kernel<<<NTOK, 256>>>(px, ln1_s + l * DMODEL, ln1_b + l * DMODEL, phdn, DMODEL);
        tf32_gemm<<<dim3(3 * DMODEL / 128, NTOK / 128), 256, SM128>>>(
            phdn, qkv_w + (size_t)l * DMODEL * 3 * DMODEL, qkv_b + l * 3 * DMODEL,
            nullptr, pqkv, NTOK, 3 * DMODEL, DMODEL, 0, 1);
        rope_kernel<<<(NTOK * NHEAD * HALFK + 255) / 256, 256>>>(pqkv);
        flash_attn<<<dim3(TPI / 64, NHEAD * NIMG), 128, FA_SMEM>>>(pqkv, pobuf);
        tf32_gemm64<<<dim3(DMODEL / 128, NTOK / 64), 256, SM64>>>(
            pobuf, proj_w + (size_t)l * DMODEL * DMODEL, proj_b + l * DMODEL,
            px, px, NTOK, DMODEL, DMODEL, 0, 0);
        layernorm_kernel<<<NTOK, 256>>>(px, ln2_s + l * DMODEL, ln2_b + l * DMODEL, phdn, DMODEL);
        tf32_gemm<<<dim3(FDIM / 128, NTOK / 128), 256, SM128>>>(
            phdn, fc1_w + (size_t)l * DMODEL * FDIM, fc1_b + l * FDIM,
            nullptr, pff, NTOK, FDIM, DMODEL, 1, 1);
        tf32_gemm64<<<dim3(DMODEL / 128, NTOK / 64), 256, SM64>>>(
            pff, fc2_w + (size_t)l * FDIM * DMODEL, fc2_b + l * DMODEL,
            px, px, NTOK, DMODEL, FDIM, 0, 0);
    }

    layernorm_kernel<<<NTOK, 256>>>(px, mn_s, mn_b, phdn, DMODEL);
    tf32_gemm64<<<dim3(FDIM / 128, (NTOK / 4) / 64), 256, SM64>>>(
        phdn, mfc1_w, mfc1_b, nullptr, pff, NTOK / 4, FDIM, FDIM, 1, 1);
    tf32_gemm64<<<dim3(OUTD / 128, (NTOK / 4) / 64), 256, SM64>>>(
        pff, mfc2_w, mfc2_b, nullptr, out, NTOK / 4, OUTD, FDIM, 0, 0);
}

// round 15
// speedup vs baseline: 1.0703x; 1.0703x over previous
#include <cuda_runtime.h>
#include <cuda_bf16.h>
#include <cstddef>
#include <cstdint>

// ---------------- fixed problem constants ----------------
#define NTOK 2048
#define DMODEL 1280
#define NHEAD 16
#define KDIM 80
#define HALFK 40
#define NLAYER 4
#define FDIM 5120
#define GPOS 48
#define OUTD 2048
#define TPI 512
#define NIMG 4

// ---------------- scratch ----------------
__device__ float g_x[NTOK * DMODEL];
__device__ float g_hdn[NTOK * DMODEL];
__device__ float g_qkv[NTOK * 3 * DMODEL];
__device__ float g_obuf[NTOK * DMODEL];
__device__ float g_ff[NTOK * FDIM];
__device__ float g_cos[NTOK * HALFK];
__device__ float g_sin[NTOK * HALFK];
__device__ int g_row[NTOK], g_col[NTOK], g_h[NTOK], g_w4[NTOK];

// ---------------- helpers ----------------
__device__ __forceinline__ float gelu_tanh(float v) {
    const float c = 0.7978845608028654f;
    float t = tanhf(c * (v + 0.044715f * v * v * v));
    return 0.5f * v * (1.0f + t);
}
__device__ __forceinline__ float warp_sum(float v) {
    #pragma unroll
    for (int o = 16; o > 0; o >>= 1) v += __shfl_xor_sync(0xffffffffu, v, o);
    return v;
}
__device__ __forceinline__ uint32_t f2tf32(float f) {
    uint32_t r;
    asm("cvt.rna.tf32.f32 %0, %1;" : "=r"(r) : "f"(f));
    return r;
}
__device__ __forceinline__ float f2tf32f(float f) {
    return __uint_as_float(f2tf32(f));
}
__device__ __forceinline__ void mma_tf32(float& c0, float& c1, float& c2, float& c3,
                                         uint32_t a0, uint32_t a1, uint32_t a2, uint32_t a3,
                                         uint32_t b0, uint32_t b1) {
    asm volatile(
        "mma.sync.aligned.m16n8k8.row.col.f32.tf32.tf32.f32 "
        "{%0,%1,%2,%3}, {%4,%5,%6,%7}, {%8,%9}, {%0,%1,%2,%3};"
        : "+f"(c0), "+f"(c1), "+f"(c2), "+f"(c3)
        : "r"(a0), "r"(a1), "r"(a2), "r"(a3), "r"(b0), "r"(b1));
}
__device__ __forceinline__ void cp16(float* smem_ptr, const float* gptr) {
    uint32_t s = (uint32_t)__cvta_generic_to_shared(smem_ptr);
    asm volatile("cp.async.cg.shared.global [%0], [%1], 16;" :: "r"(s), "l"(gptr));
}

// ---------------- token coords ----------------
__global__ void coords_kernel(const int* __restrict__ grid, int n_imgs) {
    int t = blockIdx.x * blockDim.x + threadIdx.x;
    if (t >= NTOK) return;
    int acc = 0, local = 0, h = 1, w = 1;
    for (int i = 0; i < n_imgs; i++) {
        int tpi = grid[i * 3] * grid[i * 3 + 1] * grid[i * 3 + 2];
        if (t >= acc && t < acc + tpi) {
            local = t - acc; h = grid[i * 3 + 1]; w = grid[i * 3 + 2];
        }
        acc += tpi;
    }
    int spatial = local % (h * w);
    int group = spatial / 4, intra = spatial % 4;
    int mw = w / 2;
    g_row[t] = (group / mw) * 2 + intra / 2;
    g_col[t] = (group % mw) * 2 + intra % 2;
    g_h[t] = h; g_w4[t] = w;
}

// ---------------- rope cos/sin table ----------------
__global__ void ropetab_kernel() {
    int id = blockIdx.x * blockDim.x + threadIdx.x;
    if (id >= NTOK * HALFK) return;
    int n = id / HALFK, j = id % HALFK;
    int jj = j % 20;
    float pos = (float)((j < 20) ? g_row[n] : g_col[n]);
    float inv_freq = powf(10000.0f, -(float)jj / 20.0f);
    float f = pos * inv_freq;
    g_cos[id] = cosf(f);
    g_sin[id] = sinf(f);
}

// ---------------- round fp32 -> tf32 elementwise ----------------
__global__ void round_kernel(const float* __restrict__ in, float* __restrict__ out, int n4) {
    int i = blockIdx.x * blockDim.x + threadIdx.x;
    if (i >= n4) return;
    float4 v = ((const float4*)in)[i];
    ((float4*)out)[i] = make_float4(f2tf32f(v.x), f2tf32f(v.y), f2tf32f(v.z), f2tf32f(v.w));
}

// ---------------- bilinear pos-embed add ----------------
__global__ void posembed_kernel(const float* __restrict__ pos_embed, float* __restrict__ x) {
    int n = blockIdx.x;
    int row = g_row[n], col = g_col[n], h = g_h[n], w = g_w4[n];
    float rf = (h > 1) ? (float)row * (float)(GPOS - 1) / (float)(h - 1 > 1 ? h - 1 : 1) : 0.0f;
    float cf = (w > 1) ? (float)col * (float)(GPOS - 1) / (float)(w - 1 > 1 ? w - 1 : 1) : 0.0f;
    int r0 = (int)floorf(rf), c0 = (int)floorf(cf);
    int r1 = min(r0 + 1, GPOS - 1), c1 = min(c0 + 1, GPOS - 1);
    float wr = rf - (float)r0, wc = cf - (float)c0;
    float w00 = (1 - wr) * (1 - wc), w01 = (1 - wr) * wc, w10 = wr * (1 - wc), w11 = wr * wc;
    const float* p00 = pos_embed + (size_t)(r0 * GPOS + c0) * DMODEL;
    const float* p01 = pos_embed + (size_t)(r0 * GPOS + c1) * DMODEL;
    const float* p10 = pos_embed + (size_t)(r1 * GPOS + c0) * DMODEL;
    const float* p11 = pos_embed + (size_t)(r1 * GPOS + c1) * DMODEL;
    float* xr = x + (size_t)n * DMODEL;
    for (int d = threadIdx.x; d < DMODEL; d += blockDim.x)
        xr[d] += p00[d] * w00 + p01[d] * w01 + p10[d] * w10 + p11[d] * w11;
}

// ---------------- single-pass layernorm (output tf32-rounded) ----------------
__global__ void layernorm_kernel(const float* __restrict__ x, const float* __restrict__ s,
                                 const float* __restrict__ b, float* __restrict__ out, int cols) {
    int r = blockIdx.x, tid = threadIdx.x;
    const float* xr = x + (size_t)r * cols;
    __shared__ float red[8], red2[8];
    float sum = 0.0f, ss = 0.0f;
    for (int c = tid; c < cols; c += 256) { float v = xr[c]; sum += v; ss += v * v; }
    sum = warp_sum(sum);
    ss = warp_sum(ss);
    if ((tid & 31) == 0) { red[tid >> 5] = sum; red2[tid >> 5] = ss; }
    __syncthreads();
    float tot = 0.0f, tot2 = 0.0f;
    #pragma unroll
    for (int i = 0; i < 8; i++) { tot += red[i]; tot2 += red2[i]; }
    float mu = tot / (float)cols;
    float var = fmaxf(tot2 / (float)cols - mu * mu, 0.0f);
    float inv = rsqrtf(var + 1e-6f);
    float* orow = out + (size_t)r * cols;
    for (int c = tid; c < cols; c += 256)
        orow[c] = f2tf32f((xr[c] - mu) * inv * s[c] + b[c]);
}

// ---------------- tf32 GEMM, 2-stage cp.async, 128x128 tile (R7-exact) ----------------
#define AP 36
#define BP 132
#define ASZ (128 * AP)
#define ASZ2 (64 * AP)
#define BSZ (32 * BP)
#define STAGES 2
__global__ void __launch_bounds__(256, 2)
tf32_gemm(const float* __restrict__ A, const float* __restrict__ W,
          const float* __restrict__ bias, const float* __restrict__ res,
          float* __restrict__ C, int MM, int NN, int KK, int epi, int rnd) {
    extern __shared__ float smem[];
    float* As = smem;
    float* Bs = smem + STAGES * ASZ;
    const int tid = threadIdx.x;
    const int warp = tid >> 5, lane = tid & 31;
    const int wm = warp & 1, wn = warp >> 1;
    const int g = lane >> 2, c = lane & 3;
    const int m0 = blockIdx.y * 128, n0 = blockIdx.x * 128;

    const int arow = tid >> 3, acol = (tid & 7) << 2;
    const int brow = tid >> 5, bcol = (tid & 31) << 2;

    float acc[4][4][4];
    #pragma unroll
    for (int i = 0; i < 4; i++)
        #pragma unroll
        for (int j = 0; j < 4; j++)
            #pragma unroll
            for (int r = 0; r < 4; r++) acc[i][j][r] = 0.0f;

    const int T = KK >> 5;

    #pragma unroll
    for (int i = 0; i < 4; i++) {
        cp16(As + (arow + i * 32) * AP + acol, A + (size_t)(m0 + arow + i * 32) * KK + acol);
        cp16(Bs + (brow + i * 8) * BP + bcol, W + (size_t)(brow + i * 8) * NN + n0 + bcol);
    }
    asm volatile("cp.async.commit_group;");

    for (int t = 0; t < T; ++t) {
        if (t + 1 < T) {
            const int st = (t + 1) & 1;
            const int ko = (t + 1) << 5;
            float* as = As + st * ASZ;
            float* bs = Bs + st * BSZ;
            #pragma unroll
            for (int i = 0; i < 4; i++) {
                cp16(as + (arow + i * 32) * AP + acol,
                     A + (size_t)(m0 + arow + i * 32) * KK + ko + acol);
                cp16(bs + (brow + i * 8) * BP + bcol,
                     W + (size_t)(ko + brow + i * 8) * NN + n0 + bcol);
            }
        }
        asm volatile("cp.async.commit_group;");
        asm volatile("cp.async.wait_group 1;");
        __syncthreads();

        const uint32_t* AsB = reinterpret_cast<const uint32_t*>(As + (t & 1) * ASZ);
        const float* BsF = Bs + (t & 1) * BSZ;
        #pragma unroll
        for (int kk = 0; kk < 4; kk++) {
            const int kb = kk * 8;
            uint32_t af[4][4];
            #pragma unroll
            for (int mi = 0; mi < 4; mi++) {
                int r = wm * 64 + mi * 16;
                af[mi][0] = AsB[(r + g) * AP + kb + c];
                af[mi][1] = AsB[(r + g + 8) * AP + kb + c];
                af[mi][2] = AsB[(r + g) * AP + kb + c + 4];
                af[mi][3] = AsB[(r + g + 8) * AP + kb + c + 4];
            }
            uint32_t bf[4][2];
            #pragma unroll
            for (int ni = 0; ni < 4; ni++) {
                int col = wn * 32 + ni * 8;
                bf[ni][0] = f2tf32(BsF[(kb + c) * BP + col + g]);
                bf[ni][1] = f2tf32(BsF[(kb + c + 4) * BP + col + g]);
            }
            #pragma unroll
            for (int mi = 0; mi < 4; mi++)
                #pragma unroll
                for (int ni = 0; ni < 4; ni++)
                    mma_tf32(acc[mi][ni][0], acc[mi][ni][1], acc[mi][ni][2], acc[mi][ni][3],
                             af[mi][0], af[mi][1], af[mi][2], af[mi][3],
                             bf[ni][0], bf[ni][1]);
        }
        __syncthreads();
    }

    #pragma unroll
    for (int mi = 0; mi < 4; mi++) {
        #pragma unroll
        for (int ni = 0; ni < 4; ni++) {
            int r0r = m0 + wm * 64 + mi * 16 + g;
            int cn = n0 + wn * 32 + ni * 8 + 2 * c;
            #pragma unroll
            for (int half = 0; half < 2; half++) {
                int r = r0r + half * 8;
                float v0 = acc[mi][ni][half * 2 + 0] + bias[cn];
                float v1 = acc[mi][ni][half * 2 + 1] + bias[cn + 1];
                if (res) {
                    v0 += res[(size_t)r * NN + cn];
                    v1 += res[(size_t)r * NN + cn + 1];
                }
                if (epi) { v0 = gelu_tanh(v0); v1 = gelu_tanh(v1); }
                if (rnd) { v0 = f2tf32f(v0); v1 = f2tf32f(v1); }
                *(float2*)(C + (size_t)r * NN + cn) = make_float2(v0, v1);
            }
        }
    }
}

// ---------------- tf32 GEMM, 64x128 tile (R7-exact) ----------------
__global__ void __launch_bounds__(256, 3)
tf32_gemm64(const float* __restrict__ A, const float* __restrict__ W,
            const float* __restrict__ bias, const float* __restrict__ res,
            float* __restrict__ C, int MM, int NN, int KK, int epi, int rnd) {
    extern __shared__ float smem[];
    float* As = smem;
    float* Bs = smem + STAGES * ASZ2;
    const int tid = threadIdx.x;
    const int warp = tid >> 5, lane = tid & 31;
    const int wm = warp & 1, wn = warp >> 1;
    const int g = lane >> 2, c = lane & 3;
    const int m0 = blockIdx.y * 64, n0 = blockIdx.x * 128;

    const int arow = tid >> 3, acol = (tid & 7) << 2;
    const int brow = tid >> 5, bcol = (tid & 31) << 2;

    float acc[2][4][4];
    #pragma unroll
    for (int i = 0; i < 2; i++)
        #pragma unroll
        for (int j = 0; j < 4; j++)
            #pragma unroll
            for (int r = 0; r < 4; r++) acc[i][j][r] = 0.0f;

    const int T = KK >> 5;

    #pragma unroll
    for (int i = 0; i < 2; i++)
        cp16(As + (arow + i * 32) * AP + acol, A + (size_t)(m0 + arow + i * 32) * KK + acol);
    #pragma unroll
    for (int i = 0; i < 4; i++)
        cp16(Bs + (brow + i * 8) * BP + bcol, W + (size_t)(brow + i * 8) * NN + n0 + bcol);
    asm volatile("cp.async.commit_group;");

    for (int t = 0; t < T; ++t) {
        if (t + 1 < T) {
            const int st = (t + 1) & 1;
            const int ko = (t + 1) << 5;
            float* as = As + st * ASZ2;
            float* bs = Bs + st * BSZ;
            #pragma unroll
            for (int i = 0; i < 2; i++)
                cp16(as + (arow + i * 32) * AP + acol,
                     A + (size_t)(m0 + arow + i * 32) * KK + ko + acol);
            #pragma unroll
            for (int i = 0; i < 4; i++)
                cp16(bs + (brow + i * 8) * BP + bcol,
                     W + (size_t)(ko + brow + i * 8) * NN + n0 + bcol);
        }
        asm volatile("cp.async.commit_group;");
        asm volatile("cp.async.wait_group 1;");
        __syncthreads();

        const uint32_t* AsB = reinterpret_cast<const uint32_t*>(As + (t & 1) * ASZ2);
        const float* BsF = Bs + (t & 1) * BSZ;
        #pragma unroll
        for (int kk = 0; kk < 4; kk++) {
            const int kb = kk * 8;
            uint32_t af[2][4];
            #pragma unroll
            for (int mi = 0; mi < 2; mi++) {
                int r = wm * 32 + mi * 16;
                af[mi][0] = AsB[(r + g) * AP + kb + c];
                af[mi][1] = AsB[(r + g + 8) * AP + kb + c];
                af[mi][2] = AsB[(r + g) * AP + kb + c + 4];
                af[mi][3] = AsB[(r + g + 8) * AP + kb + c + 4];
            }
            uint32_t bf[4][2];
            #pragma unroll
            for (int ni = 0; ni < 4; ni++) {
                int col = wn * 32 + ni * 8;
                bf[ni][0] = f2tf32(BsF[(kb + c) * BP + col + g]);
                bf[ni][1] = f2tf32(BsF[(kb + c + 4) * BP + col + g]);
            }
            #pragma unroll
            for (int mi = 0; mi < 2; mi++)
                #pragma unroll
                for (int ni = 0; ni < 4; ni++)
                    mma_tf32(acc[mi][ni][0], acc[mi][ni][1], acc[mi][ni][2], acc[mi][ni][3],
                             af[mi][0], af[mi][1], af[mi][2], af[mi][3],
                             bf[ni][0], bf[ni][1]);
        }
        __syncthreads();
    }

    #pragma unroll
    for (int mi = 0; mi < 2; mi++) {
        #pragma unroll
        for (int ni = 0; ni < 4; ni++) {
            int r0r = m0 + wm * 32 + mi * 16 + g;
            int cn = n0 + wn * 32 + ni * 8 + 2 * c;
            #pragma unroll
            for (int half = 0; half < 2; half++) {
                int r = r0r + half * 8;
                float v0 = acc[mi][ni][half * 2 + 0] + bias[cn];
                float v1 = acc[mi][ni][half * 2 + 1] + bias[cn + 1];
                if (res) {
                    v0 += res[(size_t)r * NN + cn];
                    v1 += res[(size_t)r * NN + cn + 1];
                }
                if (epi) { v0 = gelu_tanh(v0); v1 = gelu_tanh(v1); }
                if (rnd) { v0 = f2tf32f(v0); v1 = f2tf32f(v1); }
                *(float2*)(C + (size_t)r * NN + cn) = make_float2(v0, v1);
            }
        }
    }
}

// ---------------- rope in-place on qkv buffer ----------------
__global__ void rope_kernel(float* __restrict__ qkv) {
    int id = blockIdx.x * blockDim.x + threadIdx.x;
    if (id >= NTOK * NHEAD * HALFK) return;
    int n = id / (NHEAD * HALFK);
    int rest = id % (NHEAD * HALFK);
    int h = rest / HALFK, i = rest % HALFK;
    float c = g_cos[n * HALFK + i], s = g_sin[n * HALFK + i];
    size_t base = (size_t)n * (3 * DMODEL) + h * KDIM;
    float* q = qkv + base;
    float* k = qkv + base + DMODEL;
    float q1 = q[i], q2 = q[i + HALFK];
    q[i] = q1 * c - q2 * s;
    q[i + HALFK] = q2 * c + q1 * s;
    float k1 = k[i], k2 = k[i + HALFK];
    k[i] = k1 * c - k2 * s;
    k[i + HALFK] = k2 * c + k1 * s;
}

// ---------------- fused flash attention, 128-row q-tile ----------------
// One block = 128 q-rows of one (img, head). 256 thr = 8 warps (4m x 2n).
// Per-warp fragment work identical to the 64-row version.
#define QP 84
#define VP 88
#define PPP 68
#define FA_FLOATS (128 * QP + 64 * QP + 64 * VP + 128 * PPP + 512)
#define FA_SMEM (FA_FLOATS * 4)
#define SCALE 0.11180339887498949f
__global__ void __launch_bounds__(256)
flash_attn(const float* __restrict__ qkv, float* __restrict__ o) {
    extern __shared__ float fsm[];
    float* Qs = fsm;                 // 128 x QP
    float* Ks = Qs + 128 * QP;       // 64 x QP
    float* Vs = Ks + 64 * QP;        // 64 x VP
    float* Ps = Vs + 64 * VP;        // 128 x PPP
    float* rm = Ps + 128 * PPP;      // [128][2]
    float* rs = rm + 256;            // [128][2]

    const int h = blockIdx.y & 15, img = blockIdx.y >> 4;
    const int m0 = blockIdx.x * 128;
    const float* Qp = qkv + (size_t)img * TPI * (3 * DMODEL) + h * KDIM;
    const float* Kp = Qp + DMODEL;
    const float* Vp = Qp + 2 * DMODEL;

    const int tid = threadIdx.x;
    const int warp = tid >> 5, lane = tid & 31;
    const int wm = warp & 3, wn = warp >> 2;    // 4 m-groups x 2 n-groups
    const int g = lane >> 2, c = lane & 3;

    // load Q tile 128x80, tf32-rounded: 2560 float4, 10 per thread
    #pragma unroll
    for (int i = 0; i < 10; i++) {
        int idx = tid + i * 256;
        int row = idx / 20, c4 = (idx % 20) * 4;
        float4 q4 = *(const float4*)(Qp + (size_t)(m0 + row) * (3 * DMODEL) + c4);
        *(float4*)(Qs + row * QP + c4) =
            make_float4(f2tf32f(q4.x), f2tf32f(q4.y), f2tf32f(q4.z), f2tf32f(q4.w));
    }

    float mrow[4], lrow[4], Oa[2][5][4];
    #pragma unroll
    for (int k = 0; k < 4; k++) { mrow[k] = -1e30f; lrow[k] = 0.0f; }
    #pragma unroll
    for (int mi = 0; mi < 2; mi++)
        #pragma unroll
        for (int ni = 0; ni < 5; ni++)
            #pragma unroll
            for (int r = 0; r < 4; r++) Oa[mi][ni][r] = 0.0f;

    const uint32_t* Qb = reinterpret_cast<const uint32_t*>(Qs);
    const uint32_t* Kb = reinterpret_cast<const uint32_t*>(Ks);
    const uint32_t* Vb = reinterpret_cast<const uint32_t*>(Vs);
    const uint32_t* Pb = reinterpret_cast<const uint32_t*>(Ps);

    for (int kc = 0; kc < 8; kc++) {
        const int k0 = kc * 64;
        // load K (rounded) and V (already tf32) chunks: 1280 float4, 5 per thread
        #pragma unroll
        for (int i = 0; i < 5; i++) {
            int idx = tid + i * 256;
            int row = idx / 20, c4 = (idx % 20) * 4;
            float4 k4 = *(const float4*)(Kp + (size_t)(k0 + row) * (3 * DMODEL) + c4);
            *(float4*)(Ks + row * QP + c4) =
                make_float4(f2tf32f(k4.x), f2tf32f(k4.y), f2tf32f(k4.z), f2tf32f(k4.w));
            *(float4*)(Vs + row * VP + c4) =
                *(const float4*)(Vp + (size_t)(k0 + row) * (3 * DMODEL) + c4);
        }
        __syncthreads();

        // scores: warp tile 32x32 (rows wm*32.., cols wn*32..)
        float s[2][4][4];
        #pragma unroll
        for (int mi = 0; mi < 2; mi++)
            #pragma unroll
            for (int ni = 0; ni < 4; ni++)
                #pragma unroll
                for (int r = 0; r < 4; r++) s[mi][ni][r] = 0.0f;
        #pragma unroll
        for (int kb = 0; kb < 80; kb += 8) {
            uint32_t af[2][4];
            #pragma unroll
            for (int mi = 0; mi < 2; mi++) {
                int r = wm * 32 + mi * 16;
                af[mi][0] = Qb[(r + g) * QP + kb + c];
                af[mi][1] = Qb[(r + g + 8) * QP + kb + c];
                af[mi][2] = Qb[(r + g) * QP + kb + c + 4];
                af[mi][3] = Qb[(r + g + 8) * QP + kb + c + 4];
            }
            #pragma unroll
            for (int ni = 0; ni < 4; ni++) {
                int col = wn * 32 + ni * 8;
                uint32_t b0 = Kb[(col + g) * QP + kb + c];
                uint32_t b1 = Kb[(col + g) * QP + kb + c + 4];
                #pragma unroll
                for (int mi = 0; mi < 2; mi++)
                    mma_tf32(s[mi][ni][0], s[mi][ni][1], s[mi][ni][2], s[mi][ni][3],
                             af[mi][0], af[mi][1], af[mi][2], af[mi][3], b0, b1);
            }
        }
        float pmax[4] = {-1e30f, -1e30f, -1e30f, -1e30f};
        #pragma unroll
        for (int mi = 0; mi < 2; mi++)
            #pragma unroll
            for (int ni = 0; ni < 4; ni++)
                #pragma unroll
                for (int r = 0; r < 4; r++) {
                    s[mi][ni][r] *= SCALE;
                    int k = mi * 2 + (r >> 1);
                    pmax[k] = fmaxf(pmax[k], s[mi][ni][r]);
                }
        #pragma unroll
        for (int k = 0; k < 4; k++) {
            pmax[k] = fmaxf(pmax[k], __shfl_xor_sync(0xffffffffu, pmax[k], 1));
            pmax[k] = fmaxf(pmax[k], __shfl_xor_sync(0xffffffffu, pmax[k], 2));
        }
        if (c == 0) {
            #pragma unroll
            for (int k = 0; k < 4; k++) {
                int row = wm * 32 + (k >> 1) * 16 + (k & 1) * 8 + g;
                rm[row * 2 + wn] = pmax[k];
            }
        }
        __syncthreads();

        float alpha[4], psum[4] = {0.0f, 0.0f, 0.0f, 0.0f};
        #pragma unroll
        for (int k = 0; k < 4; k++) {
            int row = wm * 32 + (k >> 1) * 16 + (k & 1) * 8 + g;
            float mc = fmaxf(rm[row * 2], rm[row * 2 + 1]);
            float mn = fmaxf(mrow[k], mc);
            alpha[k] = __expf(mrow[k] - mn);
            mrow[k] = mn;
        }
        #pragma unroll
        for (int mi = 0; mi < 2; mi++)
            #pragma unroll
            for (int ni = 0; ni < 4; ni++)
                #pragma unroll
                for (int r = 0; r < 4; r++) {
                    int k = mi * 2 + (r >> 1);
                    float p = __expf(s[mi][ni][r] - mrow[k]);
                    s[mi][ni][r] = p;
                    psum[k] += p;
                }
        #pragma unroll
        for (int k = 0; k < 4; k++) {
            psum[k] += __shfl_xor_sync(0xffffffffu, psum[k], 1);
            psum[k] += __shfl_xor_sync(0xffffffffu, psum[k], 2);
        }
        if (c == 0) {
            #pragma unroll
            for (int k = 0; k < 4; k++) {
                int row = wm * 32 + (k >> 1) * 16 + (k & 1) * 8 + g;
                rs[row * 2 + wn] = psum[k];
            }
        }
        #pragma unroll
        for (int mi = 0; mi < 2; mi++)
            #pragma unroll
            for (int ni = 0; ni < 5; ni++)
                #pragma unroll
                for (int r = 0; r < 4; r++)
                    Oa[mi][ni][r] *= alpha[mi * 2 + (r >> 1)];
        // store P (tf32)
        #pragma unroll
        for (int mi = 0; mi < 2; mi++)
            #pragma unroll
            for (int ni = 0; ni < 4; ni++) {
                int row = wm * 32 + mi * 16 + g;
                int col = wn * 32 + ni * 8 + 2 * c;
                *(float2*)(Ps + row * PPP + col) =
                    make_float2(f2tf32f(s[mi][ni][0]), f2tf32f(s[mi][ni][1]));
                *(float2*)(Ps + (row + 8) * PPP + col) =
                    make_float2(f2tf32f(s[mi][ni][2]), f2tf32f(s[mi][ni][3]));
            }
        __syncthreads();

        #pragma unroll
        for (int k = 0; k < 4; k++) {
            int row = wm * 32 + (k >> 1) * 16 + (k & 1) * 8 + g;
            lrow[k] = lrow[k] * alpha[k] + rs[row * 2] + rs[row * 2 + 1];
        }

        // PV mma: warp tile 32x40 (cols wn*40..)
        #pragma unroll
        for (int kb = 0; kb < 64; kb += 8) {
            uint32_t af[2][4];
            #pragma unroll
            for (int mi = 0; mi < 2; mi++) {
                int r = wm * 32 + mi * 16;
                af[mi][0] = Pb[(r + g) * PPP + kb + c];
                af[mi][1] = Pb[(r + g + 8) * PPP + kb + c];
                af[mi][2] = Pb[(r + g) * PPP + kb + c + 4];
                af[mi][3] = Pb[(r + g + 8) * PPP + kb + c + 4];
            }
            #pragma unroll
            for (int ni = 0; ni < 5; ni++) {
                int col = wn * 40 + ni * 8;
                uint32_t b0 = Vb[(kb + c) * VP + col + g];
                uint32_t b1 = Vb[(kb + c + 4) * VP + col + g];
                #pragma unroll
                for (int mi = 0; mi < 2; mi++)
                    mma_tf32(Oa[mi][ni][0], Oa[mi][ni][1], Oa[mi][ni][2], Oa[mi][ni][3],
                             af[mi][0], af[mi][1], af[mi][2], af[mi][3], b0, b1);
            }
        }
        __syncthreads();
    }

    // epilogue: o = Oa / l (tf32-rounded)
    #pragma unroll
    for (int mi = 0; mi < 2; mi++)
        #pragma unroll
        for (int ni = 0; ni < 5; ni++)
            #pragma unroll
            for (int half = 0; half < 2; half++) {
                int k = mi * 2 + half;
                float inv = 1.0f / lrow[k];
                int row = img * TPI + m0 + wm * 32 + mi * 16 + g + half * 8;
                int col = h * KDIM + wn * 40 + ni * 8 + 2 * c;
                *(float2*)(o + (size_t)row * DMODEL + col) =
                    make_float2(f2tf32f(Oa[mi][ni][half * 2] * inv),
                                f2tf32f(Oa[mi][ni][half * 2 + 1] * inv));
            }
}

// ---------------- launch ----------------
extern "C" void kernel_launch(void* const* d_in, const int* in_sizes, int n_in,
                              void* d_out, int out_size) {
    const float* pixels   = (const float*)d_in[0];
    const int*   grid_thw = (const int*)d_in[1];
    const float* pos_embed= (const float*)d_in[2];
    const float* patch_w  = (const float*)d_in[3];
    const float* patch_b  = (const float*)d_in[4];
    const float* ln1_s    = (const float*)d_in[5];
    const float* ln1_b    = (const float*)d_in[6];
    const float* qkv_w    = (const float*)d_in[7];
    const float* qkv_b    = (const float*)d_in[8];
    const float* proj_w   = (const float*)d_in[9];
    const float* proj_b   = (const float*)d_in[10];
    const float* ln2_s    = (const float*)d_in[11];
    const float* ln2_b    = (const float*)d_in[12];
    const float* fc1_w    = (const float*)d_in[13];
    const float* fc1_b    = (const float*)d_in[14];
    const float* fc2_w    = (const float*)d_in[15];
    const float* fc2_b    = (const float*)d_in[16];
    const float* mn_s     = (const float*)d_in[17];
    const float* mn_b     = (const float*)d_in[18];
    const float* mfc1_w   = (const float*)d_in[19];
    const float* mfc1_b   = (const float*)d_in[20];
    const float* mfc2_w   = (const float*)d_in[21];
    const float* mfc2_b   = (const float*)d_in[22];
    float* out = (float*)d_out;

    float *px, *phdn, *pqkv, *pobuf, *pff;
    cudaGetSymbolAddress((void**)&px, g_x);
    cudaGetSymbolAddress((void**)&phdn, g_hdn);
    cudaGetSymbolAddress((void**)&pqkv, g_qkv);
    cudaGetSymbolAddress((void**)&pobuf, g_obuf);
    cudaGetSymbolAddress((void**)&pff, g_ff);

    const int SM128 = STAGES * (ASZ + BSZ) * 4;
    const int SM64  = STAGES * (ASZ2 + BSZ) * 4;
    cudaFuncSetAttribute(tf32_gemm, cudaFuncAttributeMaxDynamicSharedMemorySize, SM128);
    cudaFuncSetAttribute(tf32_gemm64, cudaFuncAttributeMaxDynamicSharedMemorySize, SM64);
    cudaFuncSetAttribute(flash_attn, cudaFuncAttributeMaxDynamicSharedMemorySize, FA_SMEM);

    int n_imgs = in_sizes[1] / 3;

    coords_kernel<<<(NTOK + 255) / 256, 256>>>(grid_thw, n_imgs);
    ropetab_kernel<<<(NTOK * HALFK + 255) / 256, 256>>>();

    round_kernel<<<(NTOK * 1536 / 4 + 255) / 256, 256>>>(pixels, pff, NTOK * 1536 / 4);
    tf32_gemm64<<<dim3(DMODEL / 128, NTOK / 64), 256, SM64>>>(
        pff, patch_w, patch_b, nullptr, px, NTOK, DMODEL, 1536, 0, 0);
    posembed_kernel<<<NTOK, 256>>>(pos_embed, px);

    for (int l = 0; l < NLAYER; ++l) {
        layernorm_kernel<<<NTOK, 256>>>(px, ln1_s + l * DMODEL, ln1_b + l * DMODEL, phdn, DMODEL);
        tf32_gemm<<<dim3(3 * DMODEL / 128, NTOK / 128), 256, SM128>>>(
            phdn, qkv_w + (size_t)l * DMODEL * 3 * DMODEL, qkv_b + l * 3 * DMODEL,
            nullptr, pqkv, NTOK, 3 * DMODEL, DMODEL, 0, 1);
        rope_kernel<<<(NTOK * NHEAD * HALFK + 255) / 256, 256>>>(pqkv);
        flash_attn<<<dim3(TPI / 128, NHEAD * NIMG), 256, FA_SMEM>>>(pqkv, pobuf);
        tf32_gemm64<<<dim3(DMODEL / 128, NTOK / 64), 256, SM64>>>(
            pobuf, proj_w + (size_t)l * DMODEL * DMODEL, proj_b + l * DMODEL,
            px, px, NTOK, DMODEL, DMODEL, 0, 0);
        layernorm_kernel<<<NTOK, 256>>>(px, ln2_s + l * DMODEL, ln2_b + l * DMODEL, phdn, DMODEL);
        tf32_gemm<<<dim3(FDIM / 128, NTOK / 128), 256, SM128>>>(
            phdn, fc1_w + (size_t)l * DMODEL * FDIM, fc1_b + l * FDIM,
            nullptr, pff, NTOK, FDIM, DMODEL, 1, 1);
        tf32_gemm64<<<dim3(DMODEL / 128, NTOK / 64), 256, SM64>>>(
            pff, fc2_w + (size_t)l * FDIM * DMODEL, fc2_b + l * DMODEL,
            px, px, NTOK, DMODEL, FDIM, 0, 0);
    }

    layernorm_kernel<<<NTOK, 256>>>(px, mn_s, mn_b, phdn, DMODEL);
    tf32_gemm64<<<dim3(FDIM / 128, (NTOK / 4) / 64), 256, SM64>>>(
        phdn, mfc1_w, mfc1_b, nullptr, pff, NTOK / 4, FDIM, FDIM, 1, 1);
    tf32_gemm64<<<dim3(OUTD / 128, (NTOK / 4) / 64), 256, SM64>>>(
        pff, mfc2_w, mfc2_b, nullptr, out, NTOK / 4, OUTD, FDIM, 0, 0);
}

// round 16
// speedup vs baseline: 1.1918x; 1.1136x over previous
#include <cuda_runtime.h>
#include <cuda_bf16.h>
#include <cstddef>
#include <cstdint>

// ---------------- fixed problem constants ----------------
#define NTOK 2048
#define DMODEL 1280
#define NHEAD 16
#define KDIM 80
#define HALFK 40
#define NLAYER 4
#define FDIM 5120
#define GPOS 48
#define OUTD 2048
#define TPI 512
#define NIMG 4

// ---------------- scratch ----------------
__device__ float g_x[NTOK * DMODEL];
__device__ float g_hdn[NTOK * DMODEL];
__device__ float g_qkv[NTOK * 3 * DMODEL];
__device__ float g_obuf[NTOK * DMODEL];
__device__ float g_ff[NTOK * FDIM];
__device__ float g_cos[NTOK * HALFK];
__device__ float g_sin[NTOK * HALFK];
__device__ int g_row[NTOK], g_col[NTOK], g_h[NTOK], g_w4[NTOK];

// ---------------- helpers ----------------
__device__ __forceinline__ float gelu_tanh(float v) {
    const float c = 0.7978845608028654f;
    float t = tanhf(c * (v + 0.044715f * v * v * v));
    return 0.5f * v * (1.0f + t);
}
__device__ __forceinline__ float warp_sum(float v) {
    #pragma unroll
    for (int o = 16; o > 0; o >>= 1) v += __shfl_xor_sync(0xffffffffu, v, o);
    return v;
}
__device__ __forceinline__ uint32_t f2tf32(float f) {
    uint32_t r;
    asm("cvt.rna.tf32.f32 %0, %1;" : "=r"(r) : "f"(f));
    return r;
}
__device__ __forceinline__ float f2tf32f(float f) {
    return __uint_as_float(f2tf32(f));
}
__device__ __forceinline__ void mma_tf32(float& c0, float& c1, float& c2, float& c3,
                                         uint32_t a0, uint32_t a1, uint32_t a2, uint32_t a3,
                                         uint32_t b0, uint32_t b1) {
    asm volatile(
        "mma.sync.aligned.m16n8k8.row.col.f32.tf32.tf32.f32 "
        "{%0,%1,%2,%3}, {%4,%5,%6,%7}, {%8,%9}, {%0,%1,%2,%3};"
        : "+f"(c0), "+f"(c1), "+f"(c2), "+f"(c3)
        : "r"(a0), "r"(a1), "r"(a2), "r"(a3), "r"(b0), "r"(b1));
}
__device__ __forceinline__ void cp16(float* smem_ptr, const float* gptr) {
    uint32_t s = (uint32_t)__cvta_generic_to_shared(smem_ptr);
    asm volatile("cp.async.cg.shared.global [%0], [%1], 16;" :: "r"(s), "l"(gptr));
}

// ---------------- token coords ----------------
__global__ void coords_kernel(const int* __restrict__ grid, int n_imgs) {
    int t = blockIdx.x * blockDim.x + threadIdx.x;
    if (t >= NTOK) return;
    int acc = 0, local = 0, h = 1, w = 1;
    for (int i = 0; i < n_imgs; i++) {
        int tpi = grid[i * 3] * grid[i * 3 + 1] * grid[i * 3 + 2];
        if (t >= acc && t < acc + tpi) {
            local = t - acc; h = grid[i * 3 + 1]; w = grid[i * 3 + 2];
        }
        acc += tpi;
    }
    int spatial = local % (h * w);
    int group = spatial / 4, intra = spatial % 4;
    int mw = w / 2;
    g_row[t] = (group / mw) * 2 + intra / 2;
    g_col[t] = (group % mw) * 2 + intra % 2;
    g_h[t] = h; g_w4[t] = w;
}

// ---------------- rope cos/sin table ----------------
__global__ void ropetab_kernel() {
    int id = blockIdx.x * blockDim.x + threadIdx.x;
    if (id >= NTOK * HALFK) return;
    int n = id / HALFK, j = id % HALFK;
    int jj = j % 20;
    float pos = (float)((j < 20) ? g_row[n] : g_col[n]);
    float inv_freq = powf(10000.0f, -(float)jj / 20.0f);
    float f = pos * inv_freq;
    g_cos[id] = cosf(f);
    g_sin[id] = sinf(f);
}

// ---------------- round fp32 -> tf32 elementwise ----------------
__global__ void round_kernel(const float* __restrict__ in, float* __restrict__ out, int n4) {
    int i = blockIdx.x * blockDim.x + threadIdx.x;
    if (i >= n4) return;
    float4 v = ((const float4*)in)[i];
    ((float4*)out)[i] = make_float4(f2tf32f(v.x), f2tf32f(v.y), f2tf32f(v.z), f2tf32f(v.w));
}

// ---------------- bilinear pos-embed add ----------------
__global__ void posembed_kernel(const float* __restrict__ pos_embed, float* __restrict__ x) {
    int n = blockIdx.x;
    int row = g_row[n], col = g_col[n], h = g_h[n], w = g_w4[n];
    float rf = (h > 1) ? (float)row * (float)(GPOS - 1) / (float)(h - 1 > 1 ? h - 1 : 1) : 0.0f;
    float cf = (w > 1) ? (float)col * (float)(GPOS - 1) / (float)(w - 1 > 1 ? w - 1 : 1) : 0.0f;
    int r0 = (int)floorf(rf), c0 = (int)floorf(cf);
    int r1 = min(r0 + 1, GPOS - 1), c1 = min(c0 + 1, GPOS - 1);
    float wr = rf - (float)r0, wc = cf - (float)c0;
    float w00 = (1 - wr) * (1 - wc), w01 = (1 - wr) * wc, w10 = wr * (1 - wc), w11 = wr * wc;
    const float* p00 = pos_embed + (size_t)(r0 * GPOS + c0) * DMODEL;
    const float* p01 = pos_embed + (size_t)(r0 * GPOS + c1) * DMODEL;
    const float* p10 = pos_embed + (size_t)(r1 * GPOS + c0) * DMODEL;
    const float* p11 = pos_embed + (size_t)(r1 * GPOS + c1) * DMODEL;
    float* xr = x + (size_t)n * DMODEL;
    for (int d = threadIdx.x; d < DMODEL; d += blockDim.x)
        xr[d] += p00[d] * w00 + p01[d] * w01 + p10[d] * w10 + p11[d] * w11;
}

// ---------------- single-pass layernorm (output tf32-rounded) ----------------
__global__ void layernorm_kernel(const float* __restrict__ x, const float* __restrict__ s,
                                 const float* __restrict__ b, float* __restrict__ out, int cols) {
    int r = blockIdx.x, tid = threadIdx.x;
    const float* xr = x + (size_t)r * cols;
    __shared__ float red[8], red2[8];
    float sum = 0.0f, ss = 0.0f;
    for (int c = tid; c < cols; c += 256) { float v = xr[c]; sum += v; ss += v * v; }
    sum = warp_sum(sum);
    ss = warp_sum(ss);
    if ((tid & 31) == 0) { red[tid >> 5] = sum; red2[tid >> 5] = ss; }
    __syncthreads();
    float tot = 0.0f, tot2 = 0.0f;
    #pragma unroll
    for (int i = 0; i < 8; i++) { tot += red[i]; tot2 += red2[i]; }
    float mu = tot / (float)cols;
    float var = fmaxf(tot2 / (float)cols - mu * mu, 0.0f);
    float inv = rsqrtf(var + 1e-6f);
    float* orow = out + (size_t)r * cols;
    for (int c = tid; c < cols; c += 256)
        orow[c] = f2tf32f((xr[c] - mu) * inv * s[c] + b[c]);
}

// ---------------- tf32 GEMM, 2-stage cp.async, 128x128 tile ----------------
// BP=136: B fragment LDS bank = (8c+g) mod 32, conflict-free (was 2-way at 132).
#define AP 36
#define BP 136
#define ASZ (128 * AP)
#define ASZ2 (64 * AP)
#define BSZ (32 * BP)
#define STAGES 2
__global__ void __launch_bounds__(256, 2)
tf32_gemm(const float* __restrict__ A, const float* __restrict__ W,
          const float* __restrict__ bias, const float* __restrict__ res,
          float* __restrict__ C, int MM, int NN, int KK, int epi, int rnd) {
    extern __shared__ float smem[];
    float* As = smem;
    float* Bs = smem + STAGES * ASZ;
    const int tid = threadIdx.x;
    const int warp = tid >> 5, lane = tid & 31;
    const int wm = warp & 1, wn = warp >> 1;
    const int g = lane >> 2, c = lane & 3;
    const int m0 = blockIdx.y * 128, n0 = blockIdx.x * 128;

    const int arow = tid >> 3, acol = (tid & 7) << 2;
    const int brow = tid >> 5, bcol = (tid & 31) << 2;

    float acc[4][4][4];
    #pragma unroll
    for (int i = 0; i < 4; i++)
        #pragma unroll
        for (int j = 0; j < 4; j++)
            #pragma unroll
            for (int r = 0; r < 4; r++) acc[i][j][r] = 0.0f;

    const int T = KK >> 5;

    #pragma unroll
    for (int i = 0; i < 4; i++) {
        cp16(As + (arow + i * 32) * AP + acol, A + (size_t)(m0 + arow + i * 32) * KK + acol);
        cp16(Bs + (brow + i * 8) * BP + bcol, W + (size_t)(brow + i * 8) * NN + n0 + bcol);
    }
    asm volatile("cp.async.commit_group;");

    for (int t = 0; t < T; ++t) {
        if (t + 1 < T) {
            const int st = (t + 1) & 1;
            const int ko = (t + 1) << 5;
            float* as = As + st * ASZ;
            float* bs = Bs + st * BSZ;
            #pragma unroll
            for (int i = 0; i < 4; i++) {
                cp16(as + (arow + i * 32) * AP + acol,
                     A + (size_t)(m0 + arow + i * 32) * KK + ko + acol);
                cp16(bs + (brow + i * 8) * BP + bcol,
                     W + (size_t)(ko + brow + i * 8) * NN + n0 + bcol);
            }
        }
        asm volatile("cp.async.commit_group;");
        asm volatile("cp.async.wait_group 1;");
        __syncthreads();

        const uint32_t* AsB = reinterpret_cast<const uint32_t*>(As + (t & 1) * ASZ);
        const float* BsF = Bs + (t & 1) * BSZ;
        #pragma unroll
        for (int kk = 0; kk < 4; kk++) {
            const int kb = kk * 8;
            uint32_t af[4][4];
            #pragma unroll
            for (int mi = 0; mi < 4; mi++) {
                int r = wm * 64 + mi * 16;
                af[mi][0] = AsB[(r + g) * AP + kb + c];
                af[mi][1] = AsB[(r + g + 8) * AP + kb + c];
                af[mi][2] = AsB[(r + g) * AP + kb + c + 4];
                af[mi][3] = AsB[(r + g + 8) * AP + kb + c + 4];
            }
            uint32_t bf[4][2];
            #pragma unroll
            for (int ni = 0; ni < 4; ni++) {
                int col = wn * 32 + ni * 8;
                bf[ni][0] = f2tf32(BsF[(kb + c) * BP + col + g]);
                bf[ni][1] = f2tf32(BsF[(kb + c + 4) * BP + col + g]);
            }
            #pragma unroll
            for (int mi = 0; mi < 4; mi++)
                #pragma unroll
                for (int ni = 0; ni < 4; ni++)
                    mma_tf32(acc[mi][ni][0], acc[mi][ni][1], acc[mi][ni][2], acc[mi][ni][3],
                             af[mi][0], af[mi][1], af[mi][2], af[mi][3],
                             bf[ni][0], bf[ni][1]);
        }
        __syncthreads();
    }

    #pragma unroll
    for (int mi = 0; mi < 4; mi++) {
        #pragma unroll
        for (int ni = 0; ni < 4; ni++) {
            int r0r = m0 + wm * 64 + mi * 16 + g;
            int cn = n0 + wn * 32 + ni * 8 + 2 * c;
            #pragma unroll
            for (int half = 0; half < 2; half++) {
                int r = r0r + half * 8;
                float v0 = acc[mi][ni][half * 2 + 0] + bias[cn];
                float v1 = acc[mi][ni][half * 2 + 1] + bias[cn + 1];
                if (res) {
                    v0 += res[(size_t)r * NN + cn];
                    v1 += res[(size_t)r * NN + cn + 1];
                }
                if (epi) { v0 = gelu_tanh(v0); v1 = gelu_tanh(v1); }
                if (rnd) { v0 = f2tf32f(v0); v1 = f2tf32f(v1); }
                *(float2*)(C + (size_t)r * NN + cn) = make_float2(v0, v1);
            }
        }
    }
}

// ---------------- tf32 GEMM, 64x128 tile ----------------
__global__ void __launch_bounds__(256, 3)
tf32_gemm64(const float* __restrict__ A, const float* __restrict__ W,
            const float* __restrict__ bias, const float* __restrict__ res,
            float* __restrict__ C, int MM, int NN, int KK, int epi, int rnd) {
    extern __shared__ float smem[];
    float* As = smem;
    float* Bs = smem + STAGES * ASZ2;
    const int tid = threadIdx.x;
    const int warp = tid >> 5, lane = tid & 31;
    const int wm = warp & 1, wn = warp >> 1;
    const int g = lane >> 2, c = lane & 3;
    const int m0 = blockIdx.y * 64, n0 = blockIdx.x * 128;

    const int arow = tid >> 3, acol = (tid & 7) << 2;
    const int brow = tid >> 5, bcol = (tid & 31) << 2;

    float acc[2][4][4];
    #pragma unroll
    for (int i = 0; i < 2; i++)
        #pragma unroll
        for (int j = 0; j < 4; j++)
            #pragma unroll
            for (int r = 0; r < 4; r++) acc[i][j][r] = 0.0f;

    const int T = KK >> 5;

    #pragma unroll
    for (int i = 0; i < 2; i++)
        cp16(As + (arow + i * 32) * AP + acol, A + (size_t)(m0 + arow + i * 32) * KK + acol);
    #pragma unroll
    for (int i = 0; i < 4; i++)
        cp16(Bs + (brow + i * 8) * BP + bcol, W + (size_t)(brow + i * 8) * NN + n0 + bcol);
    asm volatile("cp.async.commit_group;");

    for (int t = 0; t < T; ++t) {
        if (t + 1 < T) {
            const int st = (t + 1) & 1;
            const int ko = (t + 1) << 5;
            float* as = As + st * ASZ2;
            float* bs = Bs + st * BSZ;
            #pragma unroll
            for (int i = 0; i < 2; i++)
                cp16(as + (arow + i * 32) * AP + acol,
                     A + (size_t)(m0 + arow + i * 32) * KK + ko + acol);
            #pragma unroll
            for (int i = 0; i < 4; i++)
                cp16(bs + (brow + i * 8) * BP + bcol,
                     W + (size_t)(ko + brow + i * 8) * NN + n0 + bcol);
        }
        asm volatile("cp.async.commit_group;");
        asm volatile("cp.async.wait_group 1;");
        __syncthreads();

        const uint32_t* AsB = reinterpret_cast<const uint32_t*>(As + (t & 1) * ASZ2);
        const float* BsF = Bs + (t & 1) * BSZ;
        #pragma unroll
        for (int kk = 0; kk < 4; kk++) {
            const int kb = kk * 8;
            uint32_t af[2][4];
            #pragma unroll
            for (int mi = 0; mi < 2; mi++) {
                int r = wm * 32 + mi * 16;
                af[mi][0] = AsB[(r + g) * AP + kb + c];
                af[mi][1] = AsB[(r + g + 8) * AP + kb + c];
                af[mi][2] = AsB[(r + g) * AP + kb + c + 4];
                af[mi][3] = AsB[(r + g + 8) * AP + kb + c + 4];
            }
            uint32_t bf[4][2];
            #pragma unroll
            for (int ni = 0; ni < 4; ni++) {
                int col = wn * 32 + ni * 8;
                bf[ni][0] = f2tf32(BsF[(kb + c) * BP + col + g]);
                bf[ni][1] = f2tf32(BsF[(kb + c + 4) * BP + col + g]);
            }
            #pragma unroll
            for (int mi = 0; mi < 2; mi++)
                #pragma unroll
                for (int ni = 0; ni < 4; ni++)
                    mma_tf32(acc[mi][ni][0], acc[mi][ni][1], acc[mi][ni][2], acc[mi][ni][3],
                             af[mi][0], af[mi][1], af[mi][2], af[mi][3],
                             bf[ni][0], bf[ni][1]);
        }
        __syncthreads();
    }

    #pragma unroll
    for (int mi = 0; mi < 2; mi++) {
        #pragma unroll
        for (int ni = 0; ni < 4; ni++) {
            int r0r = m0 + wm * 32 + mi * 16 + g;
            int cn = n0 + wn * 32 + ni * 8 + 2 * c;
            #pragma unroll
            for (int half = 0; half < 2; half++) {
                int r = r0r + half * 8;
                float v0 = acc[mi][ni][half * 2 + 0] + bias[cn];
                float v1 = acc[mi][ni][half * 2 + 1] + bias[cn + 1];
                if (res) {
                    v0 += res[(size_t)r * NN + cn];
                    v1 += res[(size_t)r * NN + cn + 1];
                }
                if (epi) { v0 = gelu_tanh(v0); v1 = gelu_tanh(v1); }
                if (rnd) { v0 = f2tf32f(v0); v1 = f2tf32f(v1); }
                *(float2*)(C + (size_t)r * NN + cn) = make_float2(v0, v1);
            }
        }
    }
}

// ---------------- rope in-place on qkv buffer ----------------
__global__ void rope_kernel(float* __restrict__ qkv) {
    int id = blockIdx.x * blockDim.x + threadIdx.x;
    if (id >= NTOK * NHEAD * HALFK) return;
    int n = id / (NHEAD * HALFK);
    int rest = id % (NHEAD * HALFK);
    int h = rest / HALFK, i = rest % HALFK;
    float c = g_cos[n * HALFK + i], s = g_sin[n * HALFK + i];
    size_t base = (size_t)n * (3 * DMODEL) + h * KDIM;
    float* q = qkv + base;
    float* k = qkv + base + DMODEL;
    float q1 = q[i], q2 = q[i + HALFK];
    q[i] = q1 * c - q2 * s;
    q[i + HALFK] = q2 * c + q1 * s;
    float k1 = k[i], k2 = k[i + HALFK];
    k[i] = k1 * c - k2 * s;
    k[i + HALFK] = k2 * c + k1 * s;
}

// ---------------- fused flash attention, 128-row q-tile (R15-exact) ----------------
#define QP 84
#define VP 88
#define PPP 68
#define FA_FLOATS (128 * QP + 64 * QP + 64 * VP + 128 * PPP + 512)
#define FA_SMEM (FA_FLOATS * 4)
#define SCALE 0.11180339887498949f
__global__ void __launch_bounds__(256)
flash_attn(const float* __restrict__ qkv, float* __restrict__ o) {
    extern __shared__ float fsm[];
    float* Qs = fsm;
    float* Ks = Qs + 128 * QP;
    float* Vs = Ks + 64 * QP;
    float* Ps = Vs + 64 * VP;
    float* rm = Ps + 128 * PPP;
    float* rs = rm + 256;

    const int h = blockIdx.y & 15, img = blockIdx.y >> 4;
    const int m0 = blockIdx.x * 128;
    const float* Qp = qkv + (size_t)img * TPI * (3 * DMODEL) + h * KDIM;
    const float* Kp = Qp + DMODEL;
    const float* Vp = Qp + 2 * DMODEL;

    const int tid = threadIdx.x;
    const int warp = tid >> 5, lane = tid & 31;
    const int wm = warp & 3, wn = warp >> 2;
    const int g = lane >> 2, c = lane & 3;

    #pragma unroll
    for (int i = 0; i < 10; i++) {
        int idx = tid + i * 256;
        int row = idx / 20, c4 = (idx % 20) * 4;
        float4 q4 = *(const float4*)(Qp + (size_t)(m0 + row) * (3 * DMODEL) + c4);
        *(float4*)(Qs + row * QP + c4) =
            make_float4(f2tf32f(q4.x), f2tf32f(q4.y), f2tf32f(q4.z), f2tf32f(q4.w));
    }

    float mrow[4], lrow[4], Oa[2][5][4];
    #pragma unroll
    for (int k = 0; k < 4; k++) { mrow[k] = -1e30f; lrow[k] = 0.0f; }
    #pragma unroll
    for (int mi = 0; mi < 2; mi++)
        #pragma unroll
        for (int ni = 0; ni < 5; ni++)
            #pragma unroll
            for (int r = 0; r < 4; r++) Oa[mi][ni][r] = 0.0f;

    const uint32_t* Qb = reinterpret_cast<const uint32_t*>(Qs);
    const uint32_t* Kb = reinterpret_cast<const uint32_t*>(Ks);
    const uint32_t* Vb = reinterpret_cast<const uint32_t*>(Vs);
    const uint32_t* Pb = reinterpret_cast<const uint32_t*>(Ps);

    for (int kc = 0; kc < 8; kc++) {
        const int k0 = kc * 64;
        #pragma unroll
        for (int i = 0; i < 5; i++) {
            int idx = tid + i * 256;
            int row = idx / 20, c4 = (idx % 20) * 4;
            float4 k4 = *(const float4*)(Kp + (size_t)(k0 + row) * (3 * DMODEL) + c4);
            *(float4*)(Ks + row * QP + c4) =
                make_float4(f2tf32f(k4.x), f2tf32f(k4.y), f2tf32f(k4.z), f2tf32f(k4.w));
            *(float4*)(Vs + row * VP + c4) =
                *(const float4*)(Vp + (size_t)(k0 + row) * (3 * DMODEL) + c4);
        }
        __syncthreads();

        float s[2][4][4];
        #pragma unroll
        for (int mi = 0; mi < 2; mi++)
            #pragma unroll
            for (int ni = 0; ni < 4; ni++)
                #pragma unroll
                for (int r = 0; r < 4; r++) s[mi][ni][r] = 0.0f;
        #pragma unroll
        for (int kb = 0; kb < 80; kb += 8) {
            uint32_t af[2][4];
            #pragma unroll
            for (int mi = 0; mi < 2; mi++) {
                int r = wm * 32 + mi * 16;
                af[mi][0] = Qb[(r + g) * QP + kb + c];
                af[mi][1] = Qb[(r + g + 8) * QP + kb + c];
                af[mi][2] = Qb[(r + g) * QP + kb + c + 4];
                af[mi][3] = Qb[(r + g + 8) * QP + kb + c + 4];
            }
            #pragma unroll
            for (int ni = 0; ni < 4; ni++) {
                int col = wn * 32 + ni * 8;
                uint32_t b0 = Kb[(col + g) * QP + kb + c];
                uint32_t b1 = Kb[(col + g) * QP + kb + c + 4];
                #pragma unroll
                for (int mi = 0; mi < 2; mi++)
                    mma_tf32(s[mi][ni][0], s[mi][ni][1], s[mi][ni][2], s[mi][ni][3],
                             af[mi][0], af[mi][1], af[mi][2], af[mi][3], b0, b1);
            }
        }
        float pmax[4] = {-1e30f, -1e30f, -1e30f, -1e30f};
        #pragma unroll
        for (int mi = 0; mi < 2; mi++)
            #pragma unroll
            for (int ni = 0; ni < 4; ni++)
                #pragma unroll
                for (int r = 0; r < 4; r++) {
                    s[mi][ni][r] *= SCALE;
                    int k = mi * 2 + (r >> 1);
                    pmax[k] = fmaxf(pmax[k], s[mi][ni][r]);
                }
        #pragma unroll
        for (int k = 0; k < 4; k++) {
            pmax[k] = fmaxf(pmax[k], __shfl_xor_sync(0xffffffffu, pmax[k], 1));
            pmax[k] = fmaxf(pmax[k], __shfl_xor_sync(0xffffffffu, pmax[k], 2));
        }
        if (c == 0) {
            #pragma unroll
            for (int k = 0; k < 4; k++) {
                int row = wm * 32 + (k >> 1) * 16 + (k & 1) * 8 + g;
                rm[row * 2 + wn] = pmax[k];
            }
        }
        __syncthreads();

        float alpha[4], psum[4] = {0.0f, 0.0f, 0.0f, 0.0f};
        #pragma unroll
        for (int k = 0; k < 4; k++) {
            int row = wm * 32 + (k >> 1) * 16 + (k & 1) * 8 + g;
            float mc = fmaxf(rm[row * 2], rm[row * 2 + 1]);
            float mn = fmaxf(mrow[k], mc);
            alpha[k] = __expf(mrow[k] - mn);
            mrow[k] = mn;
        }
        #pragma unroll
        for (int mi = 0; mi < 2; mi++)
            #pragma unroll
            for (int ni = 0; ni < 4; ni++)
                #pragma unroll
                for (int r = 0; r < 4; r++) {
                    int k = mi * 2 + (r >> 1);
                    float p = __expf(s[mi][ni][r] - mrow[k]);
                    s[mi][ni][r] = p;
                    psum[k] += p;
                }
        #pragma unroll
        for (int k = 0; k < 4; k++) {
            psum[k] += __shfl_xor_sync(0xffffffffu, psum[k], 1);
            psum[k] += __shfl_xor_sync(0xffffffffu, psum[k], 2);
        }
        if (c == 0) {
            #pragma unroll
            for (int k = 0; k < 4; k++) {
                int row = wm * 32 + (k >> 1) * 16 + (k & 1) * 8 + g;
                rs[row * 2 + wn] = psum[k];
            }
        }
        #pragma unroll
        for (int mi = 0; mi < 2; mi++)
            #pragma unroll
            for (int ni = 0; ni < 5; ni++)
                #pragma unroll
                for (int r = 0; r < 4; r++)
                    Oa[mi][ni][r] *= alpha[mi * 2 + (r >> 1)];
        #pragma unroll
        for (int mi = 0; mi < 2; mi++)
            #pragma unroll
            for (int ni = 0; ni < 4; ni++) {
                int row = wm * 32 + mi * 16 + g;
                int col = wn * 32 + ni * 8 + 2 * c;
                *(float2*)(Ps + row * PPP + col) =
                    make_float2(f2tf32f(s[mi][ni][0]), f2tf32f(s[mi][ni][1]));
                *(float2*)(Ps + (row + 8) * PPP + col) =
                    make_float2(f2tf32f(s[mi][ni][2]), f2tf32f(s[mi][ni][3]));
            }
        __syncthreads();

        #pragma unroll
        for (int k = 0; k < 4; k++) {
            int row = wm * 32 + (k >> 1) * 16 + (k & 1) * 8 + g;
            lrow[k] = lrow[k] * alpha[k] + rs[row * 2] + rs[row * 2 + 1];
        }

        #pragma unroll
        for (int kb = 0; kb < 64; kb += 8) {
            uint32_t af[2][4];
            #pragma unroll
            for (int mi = 0; mi < 2; mi++) {
                int r = wm * 32 + mi * 16;
                af[mi][0] = Pb[(r + g) * PPP + kb + c];
                af[mi][1] = Pb[(r + g + 8) * PPP + kb + c];
                af[mi][2] = Pb[(r + g) * PPP + kb + c + 4];
                af[mi][3] = Pb[(r + g + 8) * PPP + kb + c + 4];
            }
            #pragma unroll
            for (int ni = 0; ni < 5; ni++) {
                int col = wn * 40 + ni * 8;
                uint32_t b0 = Vb[(kb + c) * VP + col + g];
                uint32_t b1 = Vb[(kb + c + 4) * VP + col + g];
                #pragma unroll
                for (int mi = 0; mi < 2; mi++)
                    mma_tf32(Oa[mi][ni][0], Oa[mi][ni][1], Oa[mi][ni][2], Oa[mi][ni][3],
                             af[mi][0], af[mi][1], af[mi][2], af[mi][3], b0, b1);
            }
        }
        __syncthreads();
    }

    #pragma unroll
    for (int mi = 0; mi < 2; mi++)
        #pragma unroll
        for (int ni = 0; ni < 5; ni++)
            #pragma unroll
            for (int half = 0; half < 2; half++) {
                int k = mi * 2 + half;
                float inv = 1.0f / lrow[k];
                int row = img * TPI + m0 + wm * 32 + mi * 16 + g + half * 8;
                int col = h * KDIM + wn * 40 + ni * 8 + 2 * c;
                *(float2*)(o + (size_t)row * DMODEL + col) =
                    make_float2(f2tf32f(Oa[mi][ni][half * 2] * inv),
                                f2tf32f(Oa[mi][ni][half * 2 + 1] * inv));
            }
}

// ---------------- launch ----------------
extern "C" void kernel_launch(void* const* d_in, const int* in_sizes, int n_in,
                              void* d_out, int out_size) {
    const float* pixels   = (const float*)d_in[0];
    const int*   grid_thw = (const int*)d_in[1];
    const float* pos_embed= (const float*)d_in[2];
    const float* patch_w  = (const float*)d_in[3];
    const float* patch_b  = (const float*)d_in[4];
    const float* ln1_s    = (const float*)d_in[5];
    const float* ln1_b    = (const float*)d_in[6];
    const float* qkv_w    = (const float*)d_in[7];
    const float* qkv_b    = (const float*)d_in[8];
    const float* proj_w   = (const float*)d_in[9];
    const float* proj_b   = (const float*)d_in[10];
    const float* ln2_s    = (const float*)d_in[11];
    const float* ln2_b    = (const float*)d_in[12];
    const float* fc1_w    = (const float*)d_in[13];
    const float* fc1_b    = (const float*)d_in[14];
    const float* fc2_w    = (const float*)d_in[15];
    const float* fc2_b    = (const float*)d_in[16];
    const float* mn_s     = (const float*)d_in[17];
    const float* mn_b     = (const float*)d_in[18];
    const float* mfc1_w   = (const float*)d_in[19];
    const float* mfc1_b   = (const float*)d_in[20];
    const float* mfc2_w   = (const float*)d_in[21];
    const float* mfc2_b   = (const float*)d_in[22];
    float* out = (float*)d_out;

    float *px, *phdn, *pqkv, *pobuf, *pff;
    cudaGetSymbolAddress((void**)&px, g_x);
    cudaGetSymbolAddress((void**)&phdn, g_hdn);
    cudaGetSymbolAddress((void**)&pqkv, g_qkv);
    cudaGetSymbolAddress((void**)&pobuf, g_obuf);
    cudaGetSymbolAddress((void**)&pff, g_ff);

    const int SM128 = STAGES * (ASZ + BSZ) * 4;
    const int SM64  = STAGES * (ASZ2 + BSZ) * 4;
    cudaFuncSetAttribute(tf32_gemm, cudaFuncAttributeMaxDynamicSharedMemorySize, SM128);
    cudaFuncSetAttribute(tf32_gemm64, cudaFuncAttributeMaxDynamicSharedMemorySize, SM64);
    cudaFuncSetAttribute(flash_attn, cudaFuncAttributeMaxDynamicSharedMemorySize, FA_SMEM);

    int n_imgs = in_sizes[1] / 3;

    coords_kernel<<<(NTOK + 255) / 256, 256>>>(grid_thw, n_imgs);
    ropetab_kernel<<<(NTOK * HALFK + 255) / 256, 256>>>();

    round_kernel<<<(NTOK * 1536 / 4 + 255) / 256, 256>>>(pixels, pff, NTOK * 1536 / 4);
    tf32_gemm64<<<dim3(DMODEL / 128, NTOK / 64), 256, SM64>>>(
        pff, patch_w, patch_b, nullptr, px, NTOK, DMODEL, 1536, 0, 0);
    posembed_kernel<<<NTOK, 256>>>(pos_embed, px);

    for (int l = 0; l < NLAYER; ++l) {
        layernorm_kernel<<<NTOK, 256>>>(px, ln1_s + l * DMODEL, ln1_b + l * DMODEL, phdn, DMODEL);
        tf32_gemm<<<dim3(3 * DMODEL / 128, NTOK / 128), 256, SM128>>>(
            phdn, qkv_w + (size_t)l * DMODEL * 3 * DMODEL, qkv_b + l * 3 * DMODEL,
            nullptr, pqkv, NTOK, 3 * DMODEL, DMODEL, 0, 1);
        rope_kernel<<<(NTOK * NHEAD * HALFK + 255) / 256, 256>>>(pqkv);
        flash_attn<<<dim3(TPI / 128, NHEAD * NIMG), 256, FA_SMEM>>>(pqkv, pobuf);
        tf32_gemm64<<<dim3(DMODEL / 128, NTOK / 64), 256, SM64>>>(
            pobuf, proj_w + (size_t)l * DMODEL * DMODEL, proj_b + l * DMODEL,
            px, px, NTOK, DMODEL, DMODEL, 0, 0);
        layernorm_kernel<<<NTOK, 256>>>(px, ln2_s + l * DMODEL, ln2_b + l * DMODEL, phdn, DMODEL);
        tf32_gemm<<<dim3(FDIM / 128, NTOK / 128), 256, SM128>>>(
            phdn, fc1_w + (size_t)l * DMODEL * FDIM, fc1_b + l * FDIM,
            nullptr, pff, NTOK, FDIM, DMODEL, 1, 1);
        tf32_gemm64<<<dim3(DMODEL / 128, NTOK / 64), 256, SM64>>>(
            pff, fc2_w + (size_t)l * FDIM * DMODEL, fc2_b + l * DMODEL,
            px, px, NTOK, DMODEL, FDIM, 0, 0);
    }

    layernorm_kernel<<<NTOK, 256>>>(px, mn_s, mn_b, phdn, DMODEL);
    tf32_gemm64<<<dim3(FDIM / 128, (NTOK / 4) / 64), 256, SM64>>>(
        phdn, mfc1_w, mfc1_b, nullptr, pff, NTOK / 4, FDIM, FDIM, 1, 1);
    tf32_gemm64<<<dim3(OUTD / 128, (NTOK / 4) / 64), 256, SM64>>>(
        pff, mfc2_w, mfc2_b, nullptr, out, NTOK / 4, OUTD, FDIM, 0, 0);
}